// round 10
// baseline (speedup 1.0000x reference)
#include <cuda_runtime.h>
#include <cuda_bf16.h>
#include <cstdint>

// ---------------------------------------------------------------------------
// RGCN2 on GB300 (sm_103): CSR gather (no atics on features) +
// bf16-split HMMA GEMMs + fused conv2+MLP weights.
// ---------------------------------------------------------------------------

#define NNODES 50000
#define DFEAT 128

static const long long OFF_DEG   = 0;                        // 4*N rsqrt scales (float)
static const long long OFF_STATS = 4LL * NNODES;             // 256
static const long long OFF_BN    = OFF_STATS + 256;          // 256
static const long long SZ        = (long long)NNODES * DFEAT;
static const long long OFF_AGGA  = OFF_BN + 256;
static const long long OFF_AGGB  = OFF_AGGA + SZ;
static const long long OFF_HA    = OFF_AGGB + SZ;
static const long long OFF_HB    = OFF_HA + SZ;
static const long long OFF_T     = OFF_HB + SZ;
static const long long OFF_WFA   = OFF_T + SZ;               // fused W (fp32 128x128)
static const long long OFF_WFB   = OFF_WFA + 16384;
static const long long OFF_BF    = OFF_WFB + 16384;          // fused bias (128)
static const long long OFF_INT   = OFF_BF + 128;             // int scratch begins here

// int scratch layout (element offsets within int region):
//   cnt   : 4*N      (cntOut0, cntIn0, cntOut1, cntIn1)
//   row0  : N+1
//   row1  : N+1
//   cur0  : N
//   cur1  : N
//   csr0  : E0 (<=600000)
//   csr1  : E1 (<=600000)
static const long long I_CNT  = 0;
static const long long I_ROW0 = 4LL * NNODES;
static const long long I_ROW1 = I_ROW0 + NNODES + 1;
static const long long I_CUR0 = I_ROW1 + NNODES + 1;
static const long long I_CUR1 = I_CUR0 + NNODES;
static const long long I_CSR0 = I_CUR1 + NNODES;
static const long long I_CSR1 = I_CSR0 + 600000;
static const long long I_END  = I_CSR1 + 600000;

__device__ float g_mem[33900000];

// ---------------------------------------------------------------------------
// utility kernels
// ---------------------------------------------------------------------------
__global__ void zero_kernel(long long off, long long n4) {
    long long i = (long long)blockIdx.x * blockDim.x + threadIdx.x;
    float4* p = reinterpret_cast<float4*>(g_mem + off);
    long long stride = (long long)gridDim.x * blockDim.x;
    float4 z = make_float4(0.f, 0.f, 0.f, 0.f);
    for (; i < n4; i += stride) p[i] = z;
}

// int degree histograms: counts src into csrc, dst into cdst
__global__ void count_kernel(const int* __restrict__ src, const int* __restrict__ dst,
                             int* __restrict__ csrc, int* __restrict__ cdst, int E) {
    int e = blockIdx.x * blockDim.x + threadIdx.x;
    if (e < E) {
        atomicAdd(&csrc[src[e]], 1);
        atomicAdd(&cdst[dst[e]], 1);
    }
}

// scales[i] = rsqrt(max(cnt[i],1)) for all 4*N counters -> OFF_DEG floats
__global__ void rsqrt_cnt_kernel(const int* __restrict__ cnt, int n) {
    int i = blockIdx.x * blockDim.x + threadIdx.x;
    if (i < n) g_mem[OFF_DEG + i] = rsqrtf(fmaxf((float)cnt[i], 1.0f));
}

// single-block exclusive scan of cnt[0..n) -> row[0..n], cur[0..n)
__global__ void __launch_bounds__(1024) scan_kernel(const int* __restrict__ cnt,
                                                    int* __restrict__ row,
                                                    int* __restrict__ cur, int n) {
    __shared__ int wsum[32];
    __shared__ int carry;
    int tid = threadIdx.x, lane = tid & 31, w = tid >> 5;
    if (tid == 0) carry = 0;
    __syncthreads();
    for (int base = 0; base < n; base += 1024) {
        int i = base + tid;
        int v = (i < n) ? cnt[i] : 0;
        int x = v;
#pragma unroll
        for (int o = 1; o < 32; o <<= 1) {
            int y = __shfl_up_sync(0xFFFFFFFFu, x, o);
            if (lane >= o) x += y;
        }
        if (lane == 31) wsum[w] = x;
        __syncthreads();
        if (w == 0) {
            int t = wsum[lane];
#pragma unroll
            for (int o = 1; o < 32; o <<= 1) {
                int y = __shfl_up_sync(0xFFFFFFFFu, t, o);
                if (lane >= o) t += y;
            }
            wsum[lane] = t;
        }
        __syncthreads();
        int incl = x + (w ? wsum[w - 1] : 0) + carry;
        if (i < n) {
            row[i] = incl - v;
            cur[i] = incl - v;
        }
        __syncthreads();
        if (tid == 1023) carry = incl;
        __syncthreads();
    }
    if (tid == 0) row[n] = carry;
}

// csr fill: csr[cur[dst]++] = src
__global__ void fill_kernel(const int* __restrict__ src, const int* __restrict__ dst,
                            int* __restrict__ cur, int* __restrict__ csr, int E) {
    int e = blockIdx.x * blockDim.x + threadIdx.x;
    if (e < E) {
        int d = dst[e];
        int p = atomicAdd(&cur[d], 1);
        csr[p] = src[e];
    }
}

// gather: out[n,:] = sIn[n] * sum_{e in row[n]..row[n+1]} X[csr[e],:] * sOut[csr[e]]
// one warp per node; lane holds 4 consecutive floats.
__global__ void gather_kernel(const int* __restrict__ row, const int* __restrict__ csr,
                              const float* __restrict__ Xg, long long x_off,
                              long long sout_off, long long sin_off,
                              long long out_off, int n) {
    int node = (int)(((long long)blockIdx.x * blockDim.x + threadIdx.x) >> 5);
    int lane = threadIdx.x & 31;
    if (node >= n) return;
    const float* X = Xg ? Xg : (g_mem + x_off);
    int e0 = __ldg(row + node), e1 = __ldg(row + node + 1);
    float ax = 0.f, ay = 0.f, az = 0.f, aw = 0.f;
    for (int e = e0; e < e1; e++) {
        int s = __ldg(csr + e);
        float sc = __ldg(&g_mem[sout_off + s]);
        float4 v = *reinterpret_cast<const float4*>(X + (size_t)s * DFEAT + lane * 4);
        ax = fmaf(v.x, sc, ax);
        ay = fmaf(v.y, sc, ay);
        az = fmaf(v.z, sc, az);
        aw = fmaf(v.w, sc, aw);
    }
    float si = __ldg(&g_mem[sin_off + node]);
    float4 o = make_float4(ax * si, ay * si, az * si, aw * si);
    *reinterpret_cast<float4*>(g_mem + out_off + (size_t)node * DFEAT + lane * 4) = o;
}

// Wf[k][j] = sum_t W2[k][t] * Wm1part[t][j]
__global__ void fuse_w_kernel(const float* __restrict__ W2, const float* __restrict__ Wm1p,
                              float* __restrict__ out) {
    int j = threadIdx.x;
    int k = blockIdx.x;
    float acc = 0.f;
#pragma unroll 4
    for (int t = 0; t < 128; t++)
        acc = fmaf(__ldg(W2 + k * 128 + t), __ldg(Wm1p + t * 128 + j), acc);
    out[k * 128 + j] = acc;
}

// bf[j] = sum_k b2r1[k]*Wm1[k][j] + b2r0[k]*Wm1[128+k][j]
__global__ void fuse_b_kernel(const float* __restrict__ b2r1, const float* __restrict__ b2r0,
                              const float* __restrict__ Wm1, float* __restrict__ bf) {
    int j = threadIdx.x;
    float acc = 0.f;
    for (int k = 0; k < 128; k++) {
        acc = fmaf(b2r1[k], Wm1[k * 128 + j], acc);
        acc = fmaf(b2r0[k], Wm1[(128 + k) * 128 + j], acc);
    }
    bf[j] = acc;
}

// ---------------------------------------------------------------------------
// mma.sync helpers (arch-agnostic PTX)
// ---------------------------------------------------------------------------
__device__ __forceinline__ uint32_t smem_u32(const void* p) {
    uint32_t a;
    asm("{ .reg .u64 t; cvta.to.shared.u64 t, %1; cvt.u32.u64 %0, t; }" : "=r"(a) : "l"(p));
    return a;
}
__device__ __forceinline__ void ldsm_x4(uint32_t addr, uint32_t* r) {
    asm volatile("ldmatrix.sync.aligned.m8n8.x4.shared.b16 {%0,%1,%2,%3}, [%4];"
                 : "=r"(r[0]), "=r"(r[1]), "=r"(r[2]), "=r"(r[3]) : "r"(addr));
}
__device__ __forceinline__ void ldsm_x4_t(uint32_t addr, uint32_t* r) {
    asm volatile("ldmatrix.sync.aligned.m8n8.x4.trans.shared.b16 {%0,%1,%2,%3}, [%4];"
                 : "=r"(r[0]), "=r"(r[1]), "=r"(r[2]), "=r"(r[3]) : "r"(addr));
}
__device__ __forceinline__ void mma16816(float* d, const uint32_t* a, const uint32_t* b) {
    asm volatile(
        "mma.sync.aligned.m16n8k16.row.col.f32.bf16.bf16.f32 "
        "{%0,%1,%2,%3}, {%4,%5,%6,%7}, {%8,%9}, {%0,%1,%2,%3};"
        : "+f"(d[0]), "+f"(d[1]), "+f"(d[2]), "+f"(d[3])
        : "r"(a[0]), "r"(a[1]), "r"(a[2]), "r"(a[3]), "r"(b[0]), "r"(b[1]));
}

// ---------------------------------------------------------------------------
// HMMA GEMM, bf16 hi/lo split (3-pass compensation), fp32 in/out.
// Y[128 rows/CTA, 128] = sum_s relu?( X_s @ W_s ) + bias
// ---------------------------------------------------------------------------
#define AS_STRIDE 136
#define SM_AH 0
#define SM_AL 34816
#define SM_BH 69632
#define SM_BL 104448
#define SMEM_BYTES 139264

template <bool RELU>
__global__ void __launch_bounds__(256) mma_gemm(
    const float* __restrict__ X0, const float* __restrict__ X1,
    const float* __restrict__ W0, const float* __restrict__ W1,
    const float* __restrict__ bias, float* __restrict__ Y,
    int M, int nsrc)
{
    extern __shared__ __align__(128) char smem[];
    uint32_t sb = smem_u32(smem);
    int tid = threadIdx.x;
    int wid = tid >> 5, lane = tid & 31;
    int row0 = blockIdx.x << 7;

    int wr = (wid & 3) * 32;
    int wc = (wid >> 2) * 64;

    float acc[2][8][4];
#pragma unroll
    for (int mi = 0; mi < 2; mi++)
#pragma unroll
        for (int ni = 0; ni < 8; ni++)
#pragma unroll
            for (int q = 0; q < 4; q++) acc[mi][ni][q] = 0.f;

    for (int s = 0; s < nsrc; s++) {
        if (s) __syncthreads();

        const float* X = s ? X1 : X0;
        const float* W = s ? W1 : W0;

        // A tile: 128x128 fp32 -> bf16 hi/lo
        for (int idx = tid; idx < 128 * 32; idx += 256) {
            int r = idx >> 5, c4 = idx & 31;
            int gr = row0 + r;
            float4 v = make_float4(0.f, 0.f, 0.f, 0.f);
            if (gr < M) v = *reinterpret_cast<const float4*>(X + (size_t)gr * DFEAT + c4 * 4);
            __nv_bfloat16 hx = __float2bfloat16(v.x), hy = __float2bfloat16(v.y);
            __nv_bfloat16 hz = __float2bfloat16(v.z), hw = __float2bfloat16(v.w);
            __nv_bfloat16 lx = __float2bfloat16(v.x - __bfloat162float(hx));
            __nv_bfloat16 ly = __float2bfloat16(v.y - __bfloat162float(hy));
            __nv_bfloat16 lz = __float2bfloat16(v.z - __bfloat162float(hz));
            __nv_bfloat16 lw = __float2bfloat16(v.w - __bfloat162float(hw));
            uint32_t off = (uint32_t)(r * AS_STRIDE + c4 * 4) * 2;
            uint2 hv, lv;
            hv.x = ((uint32_t)__bfloat16_as_ushort(hy) << 16) | __bfloat16_as_ushort(hx);
            hv.y = ((uint32_t)__bfloat16_as_ushort(hw) << 16) | __bfloat16_as_ushort(hz);
            lv.x = ((uint32_t)__bfloat16_as_ushort(ly) << 16) | __bfloat16_as_ushort(lx);
            lv.y = ((uint32_t)__bfloat16_as_ushort(lw) << 16) | __bfloat16_as_ushort(lz);
            *reinterpret_cast<uint2*>(smem + SM_AH + off) = hv;
            *reinterpret_cast<uint2*>(smem + SM_AL + off) = lv;
        }
        // B tile: W[k][n] -> bf16 hi/lo
        for (int idx = tid; idx < 128 * 32; idx += 256) {
            int k = idx >> 5, n4 = idx & 31;
            float4 w = *reinterpret_cast<const float4*>(W + (size_t)k * 128 + n4 * 4);
            __nv_bfloat16 hx = __float2bfloat16(w.x), hy = __float2bfloat16(w.y);
            __nv_bfloat16 hz = __float2bfloat16(w.z), hw = __float2bfloat16(w.w);
            __nv_bfloat16 lx = __float2bfloat16(w.x - __bfloat162float(hx));
            __nv_bfloat16 ly = __float2bfloat16(w.y - __bfloat162float(hy));
            __nv_bfloat16 lz = __float2bfloat16(w.z - __bfloat162float(hz));
            __nv_bfloat16 lw = __float2bfloat16(w.w - __bfloat162float(hw));
            uint32_t off = (uint32_t)(k * AS_STRIDE + n4 * 4) * 2;
            uint2 hv, lv;
            hv.x = ((uint32_t)__bfloat16_as_ushort(hy) << 16) | __bfloat16_as_ushort(hx);
            hv.y = ((uint32_t)__bfloat16_as_ushort(hw) << 16) | __bfloat16_as_ushort(hz);
            lv.x = ((uint32_t)__bfloat16_as_ushort(ly) << 16) | __bfloat16_as_ushort(lx);
            lv.y = ((uint32_t)__bfloat16_as_ushort(lw) << 16) | __bfloat16_as_ushort(lz);
            *reinterpret_cast<uint2*>(smem + SM_BH + off) = hv;
            *reinterpret_cast<uint2*>(smem + SM_BL + off) = lv;
        }
        __syncthreads();

#pragma unroll
        for (int p = 0; p < 3; p++) {
            uint32_t Aoff = sb + ((p == 2) ? SM_AL : SM_AH);
            uint32_t Boff = sb + ((p == 1) ? SM_BL : SM_BH);
            uint32_t a_r = wr + (lane & 15);
            uint32_t a_c = (lane >> 4) * 8;
            uint32_t b_k = (lane & 15);
            uint32_t b_c = (lane >> 4) * 8;
#pragma unroll
            for (int ks = 0; ks < 8; ks++) {
                int k0 = ks * 16;
                uint32_t a[2][4];
#pragma unroll
                for (int mi = 0; mi < 2; mi++) {
                    uint32_t addr = Aoff + ((a_r + mi * 16) * AS_STRIDE + k0 + a_c) * 2;
                    ldsm_x4(addr, a[mi]);
                }
                uint32_t b[4][4];
#pragma unroll
                for (int nj = 0; nj < 4; nj++) {
                    uint32_t addr = Boff + ((k0 + b_k) * AS_STRIDE + wc + nj * 16 + b_c) * 2;
                    ldsm_x4_t(addr, b[nj]);
                }
#pragma unroll
                for (int mi = 0; mi < 2; mi++)
#pragma unroll
                    for (int nj = 0; nj < 4; nj++) {
                        mma16816(acc[mi][nj * 2 + 0], a[mi], &b[nj][0]);
                        mma16816(acc[mi][nj * 2 + 1], a[mi], &b[nj][2]);
                    }
            }
        }
    }

    int gi = lane >> 2, qi = lane & 3;
#pragma unroll
    for (int mi = 0; mi < 2; mi++) {
#pragma unroll
        for (int half = 0; half < 2; half++) {
            int gr = row0 + wr + mi * 16 + gi + half * 8;
            if (gr >= M) continue;
            float* Yr = Y + (size_t)gr * DFEAT;
#pragma unroll
            for (int ni = 0; ni < 8; ni++) {
                int c = wc + ni * 8 + qi * 2;
                float2 bv = *reinterpret_cast<const float2*>(bias + c);
                float2 o;
                o.x = acc[mi][ni][half * 2 + 0] + bv.x;
                o.y = acc[mi][ni][half * 2 + 1] + bv.y;
                if (RELU) { o.x = fmaxf(o.x, 0.f); o.y = fmaxf(o.y, 0.f); }
                *reinterpret_cast<float2*>(Yr + c) = o;
            }
        }
    }
}

// ---------------------------------------------------------------------------
// BN column stats + head
// ---------------------------------------------------------------------------
__global__ void bn_stats_kernel(long long t_off, int M) {
    int c = threadIdx.x;
    int r0 = blockIdx.x * 128;
    int r1 = min(r0 + 128, M);
    const float* t = g_mem + t_off;
    float s = 0.f, s2 = 0.f;
    for (int i = r0; i < r1; i++) {
        float v = t[(size_t)i * DFEAT + c];
        s += v;
        s2 = fmaf(v, v, s2);
    }
    atomicAdd(&g_mem[OFF_STATS + c], s);
    atomicAdd(&g_mem[OFF_STATS + 128 + c], s2);
}

__global__ void bn_finalize_kernel(const float* __restrict__ gamma,
                                   const float* __restrict__ beta, int M) {
    int c = threadIdx.x;
    float inv_n = 1.0f / (float)M;
    float mu = g_mem[OFF_STATS + c] * inv_n;
    float var = g_mem[OFF_STATS + 128 + c] * inv_n - mu * mu;
    var = fmaxf(var, 0.f);
    float a = gamma[c] * rsqrtf(var + 1e-5f);
    g_mem[OFF_BN + c] = a;
    g_mem[OFF_BN + 128 + c] = beta[c] - mu * a;
}

__global__ void final_kernel(const float* __restrict__ Wm2, float* __restrict__ out, int M) {
    int gw = (int)(((long long)blockIdx.x * blockDim.x + threadIdx.x) >> 5);
    int lane = threadIdx.x & 31;
    if (gw >= M) return;
    int c = lane * 4;
    const float* trow = g_mem + OFF_T + (size_t)gw * DFEAT;
    float4 tv = *reinterpret_cast<const float4*>(trow + c);
    float4 av = *reinterpret_cast<const float4*>(g_mem + OFF_BN + c);
    float4 bv = *reinterpret_cast<const float4*>(g_mem + OFF_BN + 128 + c);
    float4 w0 = *reinterpret_cast<const float4*>(Wm2 + c * 2);
    float4 w1 = *reinterpret_cast<const float4*>(Wm2 + c * 2 + 4);
    float v0 = fmaxf(fmaf(tv.x, av.x, bv.x), 0.f);
    float v1 = fmaxf(fmaf(tv.y, av.y, bv.y), 0.f);
    float v2 = fmaxf(fmaf(tv.z, av.z, bv.z), 0.f);
    float v3 = fmaxf(fmaf(tv.w, av.w, bv.w), 0.f);
    float acc0 = v0 * w0.x + v1 * w0.z + v2 * w1.x + v3 * w1.z;
    float acc1 = v0 * w0.y + v1 * w0.w + v2 * w1.y + v3 * w1.w;
#pragma unroll
    for (int o = 16; o; o >>= 1) {
        acc0 += __shfl_xor_sync(0xFFFFFFFFu, acc0, o);
        acc1 += __shfl_xor_sync(0xFFFFFFFFu, acc1, o);
    }
    if (lane == 0) {
        out[(size_t)gw * 2 + 0] = acc0;
        out[(size_t)gw * 2 + 1] = acc1;
    }
}

// ---------------------------------------------------------------------------
// host
// ---------------------------------------------------------------------------
extern "C" void kernel_launch(void* const* d_in, const int* in_sizes, int n_in,
                              void* d_out, int out_size) {
    const float* xA   = (const float*)d_in[0];
    const float* xB   = (const float*)d_in[1];
    const int*   src0 = (const int*)d_in[2];
    const int*   dst0 = (const int*)d_in[3];
    const int*   src1 = (const int*)d_in[4];
    const int*   dst1 = (const int*)d_in[5];
    const float* W1r0 = (const float*)d_in[6];
    const float* b1r0 = (const float*)d_in[7];
    const float* W1r1 = (const float*)d_in[8];
    const float* b1r1 = (const float*)d_in[9];
    const float* W2r0 = (const float*)d_in[10];
    const float* b2r0 = (const float*)d_in[11];
    const float* W2r1 = (const float*)d_in[12];
    const float* b2r1 = (const float*)d_in[13];
    const float* Wm1  = (const float*)d_in[14];
    const float* gamma= (const float*)d_in[15];
    const float* beta = (const float*)d_in[16];
    const float* Wm2  = (const float*)d_in[17];
    float* out = (float*)d_out;

    int M  = in_sizes[0] / DFEAT;   // 50000
    int E0 = in_sizes[2];           // 600000
    int E1 = in_sizes[4];

    float* gb = nullptr;
    cudaGetSymbolAddress((void**)&gb, g_mem);
    int* gi = reinterpret_cast<int*>(gb + OFF_INT);

    int* cntOut0 = gi + I_CNT;
    int* cntIn0  = gi + I_CNT + NNODES;
    int* cntOut1 = gi + I_CNT + 2 * NNODES;
    int* cntIn1  = gi + I_CNT + 3 * NNODES;
    int* row0 = gi + I_ROW0;
    int* row1 = gi + I_ROW1;
    int* cur0 = gi + I_CUR0;
    int* cur1 = gi + I_CUR1;
    int* csr0 = gi + I_CSR0;
    int* csr1 = gi + I_CSR1;

    // float scale arrays at OFF_DEG (same order as counts)
    long long sOut0 = OFF_DEG;
    long long sIn0  = OFF_DEG + NNODES;
    long long sOut1 = OFF_DEG + 2LL * NNODES;
    long long sIn1  = OFF_DEG + 3LL * NNODES;

    cudaFuncSetAttribute(mma_gemm<true>, cudaFuncAttributeMaxDynamicSharedMemorySize, SMEM_BYTES);
    cudaFuncSetAttribute(mma_gemm<false>, cudaFuncAttributeMaxDynamicSharedMemorySize, SMEM_BYTES);

    // --- CSR build + degree scales ---
    zero_kernel<<<128, 256>>>(OFF_INT + I_CNT, (4LL * NNODES) / 4);  // zero int counts
    zero_kernel<<<1, 64>>>(OFF_STATS, 64);                           // zero BN stats
    count_kernel<<<(E0 + 255) / 256, 256>>>(src0, dst0, cntOut0, cntIn0, E0);
    count_kernel<<<(E1 + 255) / 256, 256>>>(src1, dst1, cntOut1, cntIn1, E1);
    rsqrt_cnt_kernel<<<(4 * NNODES + 255) / 256, 256>>>(gi + I_CNT, 4 * NNODES);
    scan_kernel<<<1, 1024>>>(cntIn0, row0, cur0, NNODES);
    scan_kernel<<<1, 1024>>>(cntIn1, row1, cur1, NNODES);
    fill_kernel<<<(E0 + 255) / 256, 256>>>(src0, dst0, cur0, csr0, E0);
    fill_kernel<<<(E1 + 255) / 256, 256>>>(src1, dst1, cur1, csr1, E1);

    // fused conv2+MLP weights (graph-independent)
    fuse_w_kernel<<<128, 128>>>(W2r1, Wm1, gb + OFF_WFA);
    fuse_w_kernel<<<128, 128>>>(W2r0, Wm1 + 128 * 128, gb + OFF_WFB);
    fuse_b_kernel<<<1, 128>>>(b2r1, b2r0, Wm1, gb + OFF_BF);

    int gat_grid = (NNODES * 32 + 255) / 256;
    int gemm_grid = (M + 127) / 128;

    // --- conv1 gathers (scales folded) ---
    gather_kernel<<<gat_grid, 256>>>(row0, csr0, xA, 0, sOut0, sIn0, OFF_AGGB, NNODES);
    gather_kernel<<<gat_grid, 256>>>(row1, csr1, xB, 0, sOut1, sIn1, OFF_AGGA, NNODES);
    mma_gemm<true><<<gemm_grid, 256, SMEM_BYTES>>>(
        gb + OFF_AGGB, nullptr, W1r0, nullptr, b1r0, gb + OFF_HB, M, 1);
    mma_gemm<true><<<gemm_grid, 256, SMEM_BYTES>>>(
        gb + OFF_AGGA, nullptr, W1r1, nullptr, b1r1, gb + OFF_HA, M, 1);

    // --- conv2 gathers ---
    gather_kernel<<<gat_grid, 256>>>(row0, csr0, nullptr, OFF_HA, sOut0, sIn0, OFF_AGGB, NNODES);
    gather_kernel<<<gat_grid, 256>>>(row1, csr1, nullptr, OFF_HB, sOut1, sIn1, OFF_AGGA, NNODES);

    // --- fused conv2+MLP: t = aggA@WfA + aggB@WfB + bf ---
    mma_gemm<false><<<gemm_grid, 256, SMEM_BYTES>>>(
        gb + OFF_AGGA, gb + OFF_AGGB, gb + OFF_WFA, gb + OFF_WFB,
        gb + OFF_BF, gb + OFF_T, M, 2);

    // --- BN + head ---
    bn_stats_kernel<<<(M + 127) / 128, 128>>>(OFF_T, M);
    bn_finalize_kernel<<<1, 128>>>(gamma, beta, M);
    final_kernel<<<(M + 7) / 8, 256>>>(Wm2, out, M);
}

// round 12
// speedup vs baseline: 1.6614x; 1.6614x over previous
#include <cuda_runtime.h>
#include <cuda_bf16.h>
#include <cstdint>

// ---------------------------------------------------------------------------
// RGCN2 on GB300 (sm_103): CSR gather + register-direct bf16-split HMMA GEMMs
// (weights pre-converted, A loaded straight into mma fragments) + fused head.
// ---------------------------------------------------------------------------

#define NNODES 50000
#define DFEAT 128

static const long long OFF_DEG   = 0;                        // 4*N rsqrt scales (float)
static const long long OFF_STATS = 4LL * NNODES;             // 256
static const long long OFF_BN    = OFF_STATS + 256;          // 256
static const long long SZ        = (long long)NNODES * DFEAT;
static const long long OFF_AGGA  = OFF_BN + 256;
static const long long OFF_AGGB  = OFF_AGGA + SZ;
static const long long OFF_HA    = OFF_AGGB + SZ;
static const long long OFF_HB    = OFF_HA + SZ;
static const long long OFF_T     = OFF_HB + SZ;
static const long long OFF_WB    = OFF_T + SZ;               // bf16 weights: 4 mats x (hi+lo) x 8192 floats
static const long long OFF_BF    = OFF_WB + 65536;           // fused bias (128)
static const long long OFF_INT   = OFF_BF + 128;

// bf16 weight slots (float offsets; each slot = 8192 floats = 16384 bf16)
static const long long WB_W1R0_HI = OFF_WB + 0;
static const long long WB_W1R0_LO = OFF_WB + 8192;
static const long long WB_W1R1_HI = OFF_WB + 16384;
static const long long WB_W1R1_LO = OFF_WB + 24576;
static const long long WB_WFA_HI  = OFF_WB + 32768;
static const long long WB_WFA_LO  = OFF_WB + 40960;
static const long long WB_WFB_HI  = OFF_WB + 49152;
static const long long WB_WFB_LO  = OFF_WB + 57344;

// int scratch (element offsets within int region)
static const long long I_CNT  = 0;                    // 4*N: cntOut0, cntIn0, cntOut1, cntIn1
static const long long I_ROW0 = 4LL * NNODES;
static const long long I_ROW1 = I_ROW0 + NNODES + 1;
static const long long I_CUR0 = I_ROW1 + NNODES + 1;
static const long long I_CUR1 = I_CUR0 + NNODES;
static const long long I_CSR0 = I_CUR1 + NNODES;
static const long long I_CSR1 = I_CSR0 + 600000;

__device__ float g_mem[33900000];

// ---------------------------------------------------------------------------
// setup kernels
// ---------------------------------------------------------------------------
// zero int counts (4N ints) + BN stats (256 floats)
__global__ void zero2_kernel() {
    long long i = (long long)blockIdx.x * blockDim.x + threadIdx.x;
    long long stride = (long long)gridDim.x * blockDim.x;
    float4* p = reinterpret_cast<float4*>(g_mem + OFF_INT);
    for (long long j = i; j < NNODES; j += stride) p[j] = make_float4(0.f, 0.f, 0.f, 0.f);
    if (i < 64) reinterpret_cast<float4*>(g_mem + OFF_STATS)[i] = make_float4(0.f, 0.f, 0.f, 0.f);
}

// both relations' degree histograms in one launch
__global__ void count_all_kernel(const int* __restrict__ src0, const int* __restrict__ dst0,
                                 const int* __restrict__ src1, const int* __restrict__ dst1,
                                 int* __restrict__ cnt, int E0, int E1) {
    int e = blockIdx.x * blockDim.x + threadIdx.x;
    if (e < E0) {
        atomicAdd(&cnt[src0[e]], 1);
        atomicAdd(&cnt[NNODES + dst0[e]], 1);
    } else if (e < E0 + E1) {
        int t = e - E0;
        atomicAdd(&cnt[2 * NNODES + src1[t]], 1);
        atomicAdd(&cnt[3 * NNODES + dst1[t]], 1);
    }
}

// blocks 0,1: exclusive scan of cntIn_r -> row_r, cur_r ; block 2: rsqrt scales
__global__ void __launch_bounds__(1024) scan_rsqrt_kernel(int* __restrict__ gi) {
    int tid = threadIdx.x;
    if (blockIdx.x == 2) {
        const int* cnt = gi + I_CNT;
        for (int i = tid; i < 4 * NNODES; i += 1024)
            g_mem[OFF_DEG + i] = rsqrtf(fmaxf((float)cnt[i], 1.0f));
        return;
    }
    int rel = blockIdx.x;
    const int* cnt = gi + I_CNT + (rel ? 3 : 1) * (long long)NNODES;
    int* row = gi + (rel ? I_ROW1 : I_ROW0);
    int* cur = gi + (rel ? I_CUR1 : I_CUR0);
    __shared__ int wsum[32];
    __shared__ int carry;
    int lane = tid & 31, w = tid >> 5;
    if (tid == 0) carry = 0;
    __syncthreads();
    for (int base = 0; base < NNODES; base += 1024) {
        int i = base + tid;
        int v = (i < NNODES) ? cnt[i] : 0;
        int x = v;
#pragma unroll
        for (int o = 1; o < 32; o <<= 1) {
            int y = __shfl_up_sync(0xFFFFFFFFu, x, o);
            if (lane >= o) x += y;
        }
        if (lane == 31) wsum[w] = x;
        __syncthreads();
        if (w == 0) {
            int t = wsum[lane];
#pragma unroll
            for (int o = 1; o < 32; o <<= 1) {
                int y = __shfl_up_sync(0xFFFFFFFFu, t, o);
                if (lane >= o) t += y;
            }
            wsum[lane] = t;
        }
        __syncthreads();
        int incl = x + (w ? wsum[w - 1] : 0) + carry;
        if (i < NNODES) {
            row[i] = incl - v;
            cur[i] = incl - v;
        }
        __syncthreads();
        if (tid == 1023) carry = incl;
        __syncthreads();
    }
    if (tid == 0) row[NNODES] = carry;
}

// both relations' csr fill in one launch
__global__ void fill_all_kernel(const int* __restrict__ src0, const int* __restrict__ dst0,
                                const int* __restrict__ src1, const int* __restrict__ dst1,
                                int* __restrict__ gi, int E0, int E1) {
    int e = blockIdx.x * blockDim.x + threadIdx.x;
    if (e < E0) {
        int p = atomicAdd(&gi[I_CUR0 + dst0[e]], 1);
        gi[I_CSR0 + p] = src0[e];
    } else if (e < E0 + E1) {
        int t = e - E0;
        int p = atomicAdd(&gi[I_CUR1 + dst1[t]], 1);
        gi[I_CSR1 + p] = src1[t];
    }
}

// gather: out[n,:] = sIn[n] * sum_e X[csr[e],:] * sOut[csr[e]]   (warp/node, 4x unroll)
__global__ void gather_kernel(const int* __restrict__ row, const int* __restrict__ csr,
                              const float* __restrict__ Xg, long long x_off,
                              long long sout_off, long long sin_off,
                              long long out_off, int n) {
    int node = (int)(((long long)blockIdx.x * blockDim.x + threadIdx.x) >> 5);
    int lane = threadIdx.x & 31;
    if (node >= n) return;
    const float* X = Xg ? Xg : (g_mem + x_off);
    int e0 = __ldg(row + node), e1 = __ldg(row + node + 1);
    float ax = 0.f, ay = 0.f, az = 0.f, aw = 0.f;
    int e = e0;
    for (; e + 4 <= e1; e += 4) {
        int s0 = __ldg(csr + e), s1 = __ldg(csr + e + 1);
        int s2 = __ldg(csr + e + 2), s3 = __ldg(csr + e + 3);
        float c0 = __ldg(&g_mem[sout_off + s0]);
        float c1 = __ldg(&g_mem[sout_off + s1]);
        float c2 = __ldg(&g_mem[sout_off + s2]);
        float c3 = __ldg(&g_mem[sout_off + s3]);
        float4 v0 = *reinterpret_cast<const float4*>(X + (size_t)s0 * DFEAT + lane * 4);
        float4 v1 = *reinterpret_cast<const float4*>(X + (size_t)s1 * DFEAT + lane * 4);
        float4 v2 = *reinterpret_cast<const float4*>(X + (size_t)s2 * DFEAT + lane * 4);
        float4 v3 = *reinterpret_cast<const float4*>(X + (size_t)s3 * DFEAT + lane * 4);
        ax = fmaf(v0.x, c0, ax); ay = fmaf(v0.y, c0, ay);
        az = fmaf(v0.z, c0, az); aw = fmaf(v0.w, c0, aw);
        ax = fmaf(v1.x, c1, ax); ay = fmaf(v1.y, c1, ay);
        az = fmaf(v1.z, c1, az); aw = fmaf(v1.w, c1, aw);
        ax = fmaf(v2.x, c2, ax); ay = fmaf(v2.y, c2, ay);
        az = fmaf(v2.z, c2, az); aw = fmaf(v2.w, c2, aw);
        ax = fmaf(v3.x, c3, ax); ay = fmaf(v3.y, c3, ay);
        az = fmaf(v3.z, c3, az); aw = fmaf(v3.w, c3, aw);
    }
    for (; e < e1; e++) {
        int s = __ldg(csr + e);
        float sc = __ldg(&g_mem[sout_off + s]);
        float4 v = *reinterpret_cast<const float4*>(X + (size_t)s * DFEAT + lane * 4);
        ax = fmaf(v.x, sc, ax); ay = fmaf(v.y, sc, ay);
        az = fmaf(v.z, sc, az); aw = fmaf(v.w, sc, aw);
    }
    float si = __ldg(&g_mem[sin_off + node]);
    float4 o = make_float4(ax * si, ay * si, az * si, aw * si);
    *reinterpret_cast<float4*>(g_mem + out_off + (size_t)node * DFEAT + lane * 4) = o;
}

// ---------------------------------------------------------------------------
// weight conversion / fusion
// ---------------------------------------------------------------------------
__device__ __forceinline__ void split_bf16(float v, __nv_bfloat16& h, __nv_bfloat16& l) {
    h = __float2bfloat16(v);
    l = __float2bfloat16(v - __bfloat162float(h));
}

// convert W1r0, W1r1 (fp32 128x128) -> bf16 hi/lo global
__global__ void wcvt_kernel(const float* __restrict__ Wa, const float* __restrict__ Wb) {
    int i = blockIdx.x * blockDim.x + threadIdx.x;  // 0..32767
    int sel = i >> 14, j = i & 16383;
    float v = sel ? __ldg(Wb + j) : __ldg(Wa + j);
    __nv_bfloat16 h, l;
    split_bf16(v, h, l);
    __nv_bfloat16* hi = reinterpret_cast<__nv_bfloat16*>(g_mem + (sel ? WB_W1R1_HI : WB_W1R0_HI));
    __nv_bfloat16* lo = reinterpret_cast<__nv_bfloat16*>(g_mem + (sel ? WB_W1R1_LO : WB_W1R0_LO));
    hi[j] = h;
    lo[j] = l;
}

// Wf[k][j] = sum_t W2[k][t] * Wm1part[t][j]  -> bf16 hi/lo
__global__ void fuse_w_kernel(const float* __restrict__ W2, const float* __restrict__ Wm1p,
                              long long hi_off, long long lo_off) {
    int j = threadIdx.x;
    int k = blockIdx.x;
    float acc = 0.f;
#pragma unroll 4
    for (int t = 0; t < 128; t++)
        acc = fmaf(__ldg(W2 + k * 128 + t), __ldg(Wm1p + t * 128 + j), acc);
    __nv_bfloat16 h, l;
    split_bf16(acc, h, l);
    reinterpret_cast<__nv_bfloat16*>(g_mem + hi_off)[k * 128 + j] = h;
    reinterpret_cast<__nv_bfloat16*>(g_mem + lo_off)[k * 128 + j] = l;
}

__global__ void fuse_b_kernel(const float* __restrict__ b2r1, const float* __restrict__ b2r0,
                              const float* __restrict__ Wm1, float* __restrict__ bf) {
    int j = threadIdx.x;
    float acc = 0.f;
    for (int k = 0; k < 128; k++) {
        acc = fmaf(b2r1[k], Wm1[k * 128 + j], acc);
        acc = fmaf(b2r0[k], Wm1[(128 + k) * 128 + j], acc);
    }
    bf[j] = acc;
}

// ---------------------------------------------------------------------------
// mma helpers
// ---------------------------------------------------------------------------
__device__ __forceinline__ uint32_t smem_u32(const void* p) {
    uint32_t a;
    asm("{ .reg .u64 t; cvta.to.shared.u64 t, %1; cvt.u32.u64 %0, t; }" : "=r"(a) : "l"(p));
    return a;
}
__device__ __forceinline__ void ldsm_x4_t(uint32_t addr, uint32_t* r) {
    asm volatile("ldmatrix.sync.aligned.m8n8.x4.trans.shared.b16 {%0,%1,%2,%3}, [%4];"
                 : "=r"(r[0]), "=r"(r[1]), "=r"(r[2]), "=r"(r[3]) : "r"(addr));
}
__device__ __forceinline__ void mma16816(float* d, const uint32_t* a, const uint32_t* b) {
    asm volatile(
        "mma.sync.aligned.m16n8k16.row.col.f32.bf16.bf16.f32 "
        "{%0,%1,%2,%3}, {%4,%5,%6,%7}, {%8,%9}, {%0,%1,%2,%3};"
        : "+f"(d[0]), "+f"(d[1]), "+f"(d[2]), "+f"(d[3])
        : "r"(a[0]), "r"(a[1]), "r"(a[2]), "r"(a[3]), "r"(b[0]), "r"(b[1]));
}
// pack float2 -> bf16x2 hi + lo residual
__device__ __forceinline__ void cvt_pair(float2 f, uint32_t& h, uint32_t& l) {
    __nv_bfloat16 hx, hy, lx, ly;
    split_bf16(f.x, hx, lx);
    split_bf16(f.y, hy, ly);
    h = ((uint32_t)__bfloat16_as_ushort(hy) << 16) | __bfloat16_as_ushort(hx);
    l = ((uint32_t)__bfloat16_as_ushort(ly) << 16) | __bfloat16_as_ushort(lx);
}

// ---------------------------------------------------------------------------
// HMMA GEMM: A fp32 from global -> register bf16 hi/lo fragments;
// B pre-converted bf16 hi/lo global -> smem (pad 136) -> ldmatrix.trans.
// Y[128/CTA,128] = sum_s relu?( X_s @ W_s ) + bias   (3-pass compensation)
// ---------------------------------------------------------------------------
#define BS_STRIDE 136
#define SM_BH 0
#define SM_BL 34816
#define SMEM_BYTES 69632

template <bool RELU>
__global__ void __launch_bounds__(256, 2) mma_gemm(
    const float* __restrict__ X0, const float* __restrict__ X1,
    const __nv_bfloat16* __restrict__ Wh0, const __nv_bfloat16* __restrict__ Wl0,
    const __nv_bfloat16* __restrict__ Wh1, const __nv_bfloat16* __restrict__ Wl1,
    const float* __restrict__ bias, float* __restrict__ Y,
    int M, int nsrc)
{
    extern __shared__ __align__(128) char smem[];
    uint32_t sb = smem_u32(smem);
    int tid = threadIdx.x;
    int wid = tid >> 5, lane = tid & 31;
    int row0 = blockIdx.x << 7;

    int wr = (wid & 3) * 32;   // warp row base
    int wc = (wid >> 2) * 64;  // warp col base

    int rr = wr + (lane >> 2); // fragment row (local)
    int q2 = (lane & 3) * 2;   // fragment k sub-offset
    uint32_t b_k = lane & 15, b_c = (lane >> 4) * 8;

    float acc[2][8][4];
#pragma unroll
    for (int mi = 0; mi < 2; mi++)
#pragma unroll
        for (int ni = 0; ni < 8; ni++)
#pragma unroll
            for (int q = 0; q < 4; q++) acc[mi][ni][q] = 0.f;

    for (int s = 0; s < nsrc; s++) {
        if (s) __syncthreads();
        const float* X = s ? X1 : X0;
        const __nv_bfloat16* Wh = s ? Wh1 : Wh0;
        const __nv_bfloat16* Wl = s ? Wl1 : Wl0;

        // copy B hi/lo into padded smem (raw uint4 moves, no conversion)
        for (int i = tid; i < 2048; i += 256) {
            int r = i >> 4, c = i & 15;
            uint32_t doff = (uint32_t)(r * BS_STRIDE + c * 8) * 2;
            *reinterpret_cast<uint4*>(smem + SM_BH + doff) =
                *reinterpret_cast<const uint4*>(Wh + r * 128 + c * 8);
            *reinterpret_cast<uint4*>(smem + SM_BL + doff) =
                *reinterpret_cast<const uint4*>(Wl + r * 128 + c * 8);
        }
        __syncthreads();

#pragma unroll
        for (int ks = 0; ks < 8; ks++) {
            int k0 = ks * 16;
            // A fragments direct from global (predicated), cvt in registers
            uint32_t ah[2][4], al[2][4];
#pragma unroll
            for (int mi = 0; mi < 2; mi++) {
                int r_ = row0 + rr + mi * 16;
                const float* base = X + (size_t)r_ * DFEAT + k0 + q2;
                float2 f0 = make_float2(0.f, 0.f), f1 = f0, f2 = f0, f3 = f0;
                if (r_ < M) {
                    f0 = *reinterpret_cast<const float2*>(base);
                    f2 = *reinterpret_cast<const float2*>(base + 8);
                }
                if (r_ + 8 < M) {
                    f1 = *reinterpret_cast<const float2*>(base + 8 * DFEAT);
                    f3 = *reinterpret_cast<const float2*>(base + 8 * DFEAT + 8);
                }
                cvt_pair(f0, ah[mi][0], al[mi][0]);
                cvt_pair(f1, ah[mi][1], al[mi][1]);
                cvt_pair(f2, ah[mi][2], al[mi][2]);
                cvt_pair(f3, ah[mi][3], al[mi][3]);
            }
#pragma unroll
            for (int nj = 0; nj < 4; nj++) {
                uint32_t boff = (uint32_t)((k0 + b_k) * BS_STRIDE + wc + nj * 16 + b_c) * 2;
                uint32_t bh[4], bl[4];
                ldsm_x4_t(sb + SM_BH + boff, bh);
                ldsm_x4_t(sb + SM_BL + boff, bl);
#pragma unroll
                for (int mi = 0; mi < 2; mi++) {
                    mma16816(acc[mi][nj * 2 + 0], ah[mi], &bh[0]);
                    mma16816(acc[mi][nj * 2 + 1], ah[mi], &bh[2]);
                    mma16816(acc[mi][nj * 2 + 0], ah[mi], &bl[0]);
                    mma16816(acc[mi][nj * 2 + 1], ah[mi], &bl[2]);
                    mma16816(acc[mi][nj * 2 + 0], al[mi], &bh[0]);
                    mma16816(acc[mi][nj * 2 + 1], al[mi], &bh[2]);
                }
            }
        }
    }

    // epilogue
    int gi = lane >> 2, qi = lane & 3;
#pragma unroll
    for (int mi = 0; mi < 2; mi++) {
#pragma unroll
        for (int half = 0; half < 2; half++) {
            int gr = row0 + wr + mi * 16 + gi + half * 8;
            if (gr >= M) continue;
            float* Yr = Y + (size_t)gr * DFEAT;
#pragma unroll
            for (int ni = 0; ni < 8; ni++) {
                int c = wc + ni * 8 + qi * 2;
                float2 bv = *reinterpret_cast<const float2*>(bias + c);
                float2 o;
                o.x = acc[mi][ni][half * 2 + 0] + bv.x;
                o.y = acc[mi][ni][half * 2 + 1] + bv.y;
                if (RELU) { o.x = fmaxf(o.x, 0.f); o.y = fmaxf(o.y, 0.f); }
                *reinterpret_cast<float2*>(Yr + c) = o;
            }
        }
    }
}

// ---------------------------------------------------------------------------
// BN column stats + head
// ---------------------------------------------------------------------------
__global__ void bn_stats_kernel(long long t_off, int M) {
    int c = threadIdx.x;
    int r0 = blockIdx.x * 128;
    int r1 = min(r0 + 128, M);
    const float* t = g_mem + t_off;
    float s = 0.f, s2 = 0.f;
    for (int i = r0; i < r1; i++) {
        float v = t[(size_t)i * DFEAT + c];
        s += v;
        s2 = fmaf(v, v, s2);
    }
    atomicAdd(&g_mem[OFF_STATS + c], s);
    atomicAdd(&g_mem[OFF_STATS + 128 + c], s2);
}

__global__ void bn_finalize_kernel(const float* __restrict__ gamma,
                                   const float* __restrict__ beta, int M) {
    int c = threadIdx.x;
    float inv_n = 1.0f / (float)M;
    float mu = g_mem[OFF_STATS + c] * inv_n;
    float var = g_mem[OFF_STATS + 128 + c] * inv_n - mu * mu;
    var = fmaxf(var, 0.f);
    float a = gamma[c] * rsqrtf(var + 1e-5f);
    g_mem[OFF_BN + c] = a;
    g_mem[OFF_BN + 128 + c] = beta[c] - mu * a;
}

__global__ void final_kernel(const float* __restrict__ Wm2, float* __restrict__ out, int M) {
    int gw = (int)(((long long)blockIdx.x * blockDim.x + threadIdx.x) >> 5);
    int lane = threadIdx.x & 31;
    if (gw >= M) return;
    int c = lane * 4;
    const float* trow = g_mem + OFF_T + (size_t)gw * DFEAT;
    float4 tv = *reinterpret_cast<const float4*>(trow + c);
    float4 av = *reinterpret_cast<const float4*>(g_mem + OFF_BN + c);
    float4 bv = *reinterpret_cast<const float4*>(g_mem + OFF_BN + 128 + c);
    float4 w0 = *reinterpret_cast<const float4*>(Wm2 + c * 2);
    float4 w1 = *reinterpret_cast<const float4*>(Wm2 + c * 2 + 4);
    float v0 = fmaxf(fmaf(tv.x, av.x, bv.x), 0.f);
    float v1 = fmaxf(fmaf(tv.y, av.y, bv.y), 0.f);
    float v2 = fmaxf(fmaf(tv.z, av.z, bv.z), 0.f);
    float v3 = fmaxf(fmaf(tv.w, av.w, bv.w), 0.f);
    float acc0 = v0 * w0.x + v1 * w0.z + v2 * w1.x + v3 * w1.z;
    float acc1 = v0 * w0.y + v1 * w0.w + v2 * w1.y + v3 * w1.w;
#pragma unroll
    for (int o = 16; o; o >>= 1) {
        acc0 += __shfl_xor_sync(0xFFFFFFFFu, acc0, o);
        acc1 += __shfl_xor_sync(0xFFFFFFFFu, acc1, o);
    }
    if (lane == 0) {
        out[(size_t)gw * 2 + 0] = acc0;
        out[(size_t)gw * 2 + 1] = acc1;
    }
}

// ---------------------------------------------------------------------------
// host
// ---------------------------------------------------------------------------
extern "C" void kernel_launch(void* const* d_in, const int* in_sizes, int n_in,
                              void* d_out, int out_size) {
    const float* xA   = (const float*)d_in[0];
    const float* xB   = (const float*)d_in[1];
    const int*   src0 = (const int*)d_in[2];
    const int*   dst0 = (const int*)d_in[3];
    const int*   src1 = (const int*)d_in[4];
    const int*   dst1 = (const int*)d_in[5];
    const float* W1r0 = (const float*)d_in[6];
    const float* b1r0 = (const float*)d_in[7];
    const float* W1r1 = (const float*)d_in[8];
    const float* b1r1 = (const float*)d_in[9];
    const float* W2r0 = (const float*)d_in[10];
    const float* b2r0 = (const float*)d_in[11];
    const float* W2r1 = (const float*)d_in[12];
    const float* b2r1 = (const float*)d_in[13];
    const float* Wm1  = (const float*)d_in[14];
    const float* gamma= (const float*)d_in[15];
    const float* beta = (const float*)d_in[16];
    const float* Wm2  = (const float*)d_in[17];
    float* out = (float*)d_out;

    int M  = in_sizes[0] / DFEAT;   // 50000
    int E0 = in_sizes[2];
    int E1 = in_sizes[4];

    float* gb = nullptr;
    cudaGetSymbolAddress((void**)&gb, g_mem);
    int* gi = reinterpret_cast<int*>(gb + OFF_INT);

    int* row0 = gi + I_ROW0;
    int* row1 = gi + I_ROW1;
    int* csr0 = gi + I_CSR0;
    int* csr1 = gi + I_CSR1;

    long long sOut0 = OFF_DEG;
    long long sIn0  = OFF_DEG + NNODES;
    long long sOut1 = OFF_DEG + 2LL * NNODES;
    long long sIn1  = OFF_DEG + 3LL * NNODES;

    cudaFuncSetAttribute(mma_gemm<true>, cudaFuncAttributeMaxDynamicSharedMemorySize, SMEM_BYTES);
    cudaFuncSetAttribute(mma_gemm<false>, cudaFuncAttributeMaxDynamicSharedMemorySize, SMEM_BYTES);

    const __nv_bfloat16* w1r0h = reinterpret_cast<const __nv_bfloat16*>(gb + WB_W1R0_HI);
    const __nv_bfloat16* w1r0l = reinterpret_cast<const __nv_bfloat16*>(gb + WB_W1R0_LO);
    const __nv_bfloat16* w1r1h = reinterpret_cast<const __nv_bfloat16*>(gb + WB_W1R1_HI);
    const __nv_bfloat16* w1r1l = reinterpret_cast<const __nv_bfloat16*>(gb + WB_W1R1_LO);
    const __nv_bfloat16* wfah  = reinterpret_cast<const __nv_bfloat16*>(gb + WB_WFA_HI);
    const __nv_bfloat16* wfal  = reinterpret_cast<const __nv_bfloat16*>(gb + WB_WFA_LO);
    const __nv_bfloat16* wfbh  = reinterpret_cast<const __nv_bfloat16*>(gb + WB_WFB_HI);
    const __nv_bfloat16* wfbl  = reinterpret_cast<const __nv_bfloat16*>(gb + WB_WFB_LO);

    int EA = E0 + E1;
    int gat_grid = (NNODES * 32 + 255) / 256;
    int gemm_grid = (M + 127) / 128;

    // --- CSR build + scales (4 launches) ---
    zero2_kernel<<<128, 256>>>();
    count_all_kernel<<<(EA + 255) / 256, 256>>>(src0, dst0, src1, dst1, gi + I_CNT, E0, E1);
    scan_rsqrt_kernel<<<3, 1024>>>(gi);
    fill_all_kernel<<<(EA + 255) / 256, 256>>>(src0, dst0, src1, dst1, gi, E0, E1);

    // --- conv1 ---
    gather_kernel<<<gat_grid, 256>>>(row0, csr0, xA, 0, sOut0, sIn0, OFF_AGGB, NNODES);
    gather_kernel<<<gat_grid, 256>>>(row1, csr1, xB, 0, sOut1, sIn1, OFF_AGGA, NNODES);
    wcvt_kernel<<<128, 256>>>(W1r0, W1r1);
    mma_gemm<true><<<gemm_grid, 256, SMEM_BYTES>>>(
        gb + OFF_AGGB, nullptr, w1r0h, w1r0l, nullptr, nullptr, b1r0, gb + OFF_HB, M, 1);
    mma_gemm<true><<<gemm_grid, 256, SMEM_BYTES>>>(
        gb + OFF_AGGA, nullptr, w1r1h, w1r1l, nullptr, nullptr, b1r1, gb + OFF_HA, M, 1);

    // --- conv2 gathers ---
    gather_kernel<<<gat_grid, 256>>>(row0, csr0, nullptr, OFF_HA, sOut0, sIn0, OFF_AGGB, NNODES);
    gather_kernel<<<gat_grid, 256>>>(row1, csr1, nullptr, OFF_HB, sOut1, sIn1, OFF_AGGA, NNODES);

    // --- fused conv2+MLP weights + bias ---
    fuse_w_kernel<<<128, 128>>>(W2r1, Wm1, WB_WFA_HI, WB_WFA_LO);
    fuse_w_kernel<<<128, 128>>>(W2r0, Wm1 + 128 * 128, WB_WFB_HI, WB_WFB_LO);
    fuse_b_kernel<<<1, 128>>>(b2r1, b2r0, Wm1, gb + OFF_BF);

    // --- fused GEMM: t = aggA@WfA + aggB@WfB + bf ---
    mma_gemm<false><<<gemm_grid, 256, SMEM_BYTES>>>(
        gb + OFF_AGGA, gb + OFF_AGGB, wfah, wfal, wfbh, wfbl,
        gb + OFF_BF, gb + OFF_T, M, 2);

    // --- BN + head ---
    bn_stats_kernel<<<(M + 127) / 128, 128>>>(OFF_T, M);
    bn_finalize_kernel<<<1, 128>>>(gamma, beta, M);
    final_kernel<<<(M + 7) / 8, 256>>>(Wm2, out, M);
}

// round 15
// speedup vs baseline: 1.8063x; 1.0872x over previous
#include <cuda_runtime.h>
#include <cuda_bf16.h>
#include <cstdint>

// ---------------------------------------------------------------------------
// RGCN2 on GB300 (sm_103): CSR gather emitting bf16 hi/lo pair-planes +
// HMMA GEMMs reading pre-split A/B + fused conv2+MLP weights + BN head.
// ---------------------------------------------------------------------------

#define NNODES 50000
#define DFEAT 128
#define NCHUNK 196   // ceil(NNODES/256)

static const long long OFF_DEG   = 0;                        // 4*N rsqrt scales (float)
static const long long OFF_STATS = 4LL * NNODES;             // 256
static const long long OFF_BN    = OFF_STATS + 256;          // 256
static const long long SZ        = (long long)NNODES * DFEAT;
static const long long OFF_AGGA  = OFF_BN + 256;             // pair-plane {hi,lo} uint2
static const long long OFF_AGGB  = OFF_AGGA + SZ;            // pair-plane
static const long long OFF_HA    = OFF_AGGB + SZ;            // fp32
static const long long OFF_HB    = OFF_HA + SZ;              // fp32
static const long long OFF_T     = OFF_HB + SZ;              // fp32
static const long long OFF_WB    = OFF_T + SZ;               // bf16 weight planes
static const long long OFF_BF    = OFF_WB + 65536;           // fused bias (128)
static const long long OFF_INT   = OFF_BF + 128;

// bf16 weight slots (float offsets; each slot = 8192 floats = 16384 bf16)
static const long long WB_W1R0_HI = OFF_WB + 0;
static const long long WB_W1R0_LO = OFF_WB + 8192;
static const long long WB_W1R1_HI = OFF_WB + 16384;
static const long long WB_W1R1_LO = OFF_WB + 24576;
static const long long WB_WFA_HI  = OFF_WB + 32768;
static const long long WB_WFA_LO  = OFF_WB + 40960;
static const long long WB_WFB_HI  = OFF_WB + 49152;
static const long long WB_WFB_LO  = OFF_WB + 57344;

// int scratch (element offsets within int region)
static const long long I_CNT  = 0;                    // 4*N
static const long long I_ROW0 = 4LL * NNODES;
static const long long I_ROW1 = I_ROW0 + NNODES + 1;
static const long long I_CUR0 = I_ROW1 + NNODES + 1;
static const long long I_CUR1 = I_CUR0 + NNODES;
static const long long I_CSR0 = I_CUR1 + NNODES;
static const long long I_CSR1 = I_CSR0 + 600000;
static const long long I_PART = I_CSR1 + 600000;      // 2*NCHUNK chunk partials

__device__ float g_mem[33900000];

__device__ __forceinline__ void split_bf16(float v, __nv_bfloat16& h, __nv_bfloat16& l) {
    h = __float2bfloat16(v);
    l = __float2bfloat16(v - __bfloat162float(h));
}
__device__ __forceinline__ uint32_t pack2(__nv_bfloat16 a, __nv_bfloat16 b) {
    return ((uint32_t)__bfloat16_as_ushort(b) << 16) | __bfloat16_as_ushort(a);
}

// ---------------------------------------------------------------------------
// setup kernels
// ---------------------------------------------------------------------------
__global__ void zero2_kernel() {
    long long i = (long long)blockIdx.x * blockDim.x + threadIdx.x;
    long long stride = (long long)gridDim.x * blockDim.x;
    float4* p = reinterpret_cast<float4*>(g_mem + OFF_INT);
    for (long long j = i; j < NNODES; j += stride) p[j] = make_float4(0.f, 0.f, 0.f, 0.f);
    if (i < 64) reinterpret_cast<float4*>(g_mem + OFF_STATS)[i] = make_float4(0.f, 0.f, 0.f, 0.f);
}

__global__ void count_all_kernel(const int* __restrict__ src0, const int* __restrict__ dst0,
                                 const int* __restrict__ src1, const int* __restrict__ dst1,
                                 int* __restrict__ cnt, int E0, int E1) {
    int e = blockIdx.x * blockDim.x + threadIdx.x;
    if (e < E0) {
        atomicAdd(&cnt[src0[e]], 1);
        atomicAdd(&cnt[NNODES + dst0[e]], 1);
    } else if (e < E0 + E1) {
        int t = e - E0;
        atomicAdd(&cnt[2 * NNODES + src1[t]], 1);
        atomicAdd(&cnt[3 * NNODES + dst1[t]], 1);
    }
}

// grid = 2*NCHUNK: per-chunk in-degree sums; plus grid-stride rsqrt of all 4N counts
__global__ void __launch_bounds__(256) scan_sums_kernel(int* __restrict__ gi) {
    __shared__ int ws[8];
    int b = blockIdx.x, tid = threadIdx.x;
    int rel = b / NCHUNK, c = b % NCHUNK;
    const int* cnt = gi + I_CNT + (rel ? 3 : 1) * (long long)NNODES;
    int i = c * 256 + tid;
    int v = (i < NNODES) ? cnt[i] : 0;
    int x = v;
#pragma unroll
    for (int o = 16; o; o >>= 1) x += __shfl_down_sync(0xFFFFFFFFu, x, o);
    if ((tid & 31) == 0) ws[tid >> 5] = x;
    __syncthreads();
    if (tid == 0) {
        int s = 0;
#pragma unroll
        for (int w = 0; w < 8; w++) s += ws[w];
        gi[I_PART + b] = s;
    }
    // rsqrt scales (grid-stride over all 4N counts)
    const int* call = gi + I_CNT;
    for (long long j = (long long)b * 256 + tid; j < 4LL * NNODES; j += 2LL * NCHUNK * 256)
        g_mem[OFF_DEG + j] = rsqrtf(fmaxf((float)call[j], 1.0f));
}

// 1 block, 512 threads: inclusive scan of chunk partials per relation -> chunk offsets + row[N]
__global__ void __launch_bounds__(512) scan_offsets_kernel(int* __restrict__ gi) {
    __shared__ int sm[512];
    int tid = threadIdx.x;
    int rel = tid >> 8, t = tid & 255;
    sm[tid] = (t < NCHUNK) ? gi[I_PART + rel * NCHUNK + t] : 0;
    __syncthreads();
    for (int o = 1; o < 256; o <<= 1) {
        int add = (t >= o) ? sm[rel * 256 + t - o] : 0;
        __syncthreads();
        sm[tid] += add;
        __syncthreads();
    }
    if (t < NCHUNK) gi[I_PART + rel * NCHUNK + t] = t ? sm[rel * 256 + t - 1] : 0;
    if (t == 0) gi[(rel ? I_ROW1 : I_ROW0) + NNODES] = sm[rel * 256 + NCHUNK - 1];
}

// grid = 2*NCHUNK: block-exclusive scan of chunk + chunk offset -> row, cur
__global__ void __launch_bounds__(256) scan_expand_kernel(int* __restrict__ gi) {
    __shared__ int ws[8];
    int b = blockIdx.x, tid = threadIdx.x;
    int lane = tid & 31, w = tid >> 5;
    int rel = b / NCHUNK, c = b % NCHUNK;
    const int* cnt = gi + I_CNT + (rel ? 3 : 1) * (long long)NNODES;
    int* row = gi + (rel ? I_ROW1 : I_ROW0);
    int* cur = gi + (rel ? I_CUR1 : I_CUR0);
    int i = c * 256 + tid;
    int v = (i < NNODES) ? cnt[i] : 0;
    int x = v;
#pragma unroll
    for (int o = 1; o < 32; o <<= 1) {
        int y = __shfl_up_sync(0xFFFFFFFFu, x, o);
        if (lane >= o) x += y;
    }
    if (lane == 31) ws[w] = x;
    __syncthreads();
    if (w == 0) {
        int t = (lane < 8) ? ws[lane] : 0;
#pragma unroll
        for (int o = 1; o < 8; o <<= 1) {
            int y = __shfl_up_sync(0xFFFFFFFFu, t, o);
            if (lane >= o) t += y;
        }
        if (lane < 8) ws[lane] = t;
    }
    __syncthreads();
    int excl = x - v + (w ? ws[w - 1] : 0) + gi[I_PART + b];
    if (i < NNODES) {
        row[i] = excl;
        cur[i] = excl;
    }
}

__global__ void fill_all_kernel(const int* __restrict__ src0, const int* __restrict__ dst0,
                                const int* __restrict__ src1, const int* __restrict__ dst1,
                                int* __restrict__ gi, int E0, int E1) {
    int e = blockIdx.x * blockDim.x + threadIdx.x;
    if (e < E0) {
        int p = atomicAdd(&gi[I_CUR0 + dst0[e]], 1);
        gi[I_CSR0 + p] = src0[e];
    } else if (e < E0 + E1) {
        int t = e - E0;
        int p = atomicAdd(&gi[I_CUR1 + dst1[t]], 1);
        gi[I_CSR1 + p] = src1[t];
    }
}

// merged gather (both relations): out pair-plane {hi,lo} uint2 slots.
// rel0: X0 -> out0 (csr0);  rel1: X1 -> out1 (csr1)
__global__ void gather2_kernel(const float* __restrict__ X0g, const float* __restrict__ X1g,
                               long long x0_off, long long x1_off,
                               const int* __restrict__ row0, const int* __restrict__ csr0,
                               const int* __restrict__ row1, const int* __restrict__ csr1,
                               long long so0, long long si0, long long out0,
                               long long so1, long long si1, long long out1) {
    int gw = (int)(((long long)blockIdx.x * blockDim.x + threadIdx.x) >> 5);
    int lane = threadIdx.x & 31;
    if (gw >= 2 * NNODES) return;
    int rel = (gw >= NNODES);
    int node = gw - (rel ? NNODES : 0);
    const int* row = rel ? row1 : row0;
    const int* csr = rel ? csr1 : csr0;
    const float* Xg = rel ? X1g : X0g;
    const float* X = Xg ? Xg : (g_mem + (rel ? x1_off : x0_off));
    long long so = rel ? so1 : so0;
    long long si = rel ? si1 : si0;
    long long oo = rel ? out1 : out0;

    int e0 = __ldg(row + node), e1 = __ldg(row + node + 1);
    float ax = 0.f, ay = 0.f, az = 0.f, aw = 0.f;
    int e = e0;
    for (; e + 4 <= e1; e += 4) {
        int s0 = __ldg(csr + e), s1 = __ldg(csr + e + 1);
        int s2 = __ldg(csr + e + 2), s3 = __ldg(csr + e + 3);
        float c0 = __ldg(&g_mem[so + s0]);
        float c1 = __ldg(&g_mem[so + s1]);
        float c2 = __ldg(&g_mem[so + s2]);
        float c3 = __ldg(&g_mem[so + s3]);
        float4 v0 = *reinterpret_cast<const float4*>(X + (size_t)s0 * DFEAT + lane * 4);
        float4 v1 = *reinterpret_cast<const float4*>(X + (size_t)s1 * DFEAT + lane * 4);
        float4 v2 = *reinterpret_cast<const float4*>(X + (size_t)s2 * DFEAT + lane * 4);
        float4 v3 = *reinterpret_cast<const float4*>(X + (size_t)s3 * DFEAT + lane * 4);
        ax = fmaf(v0.x, c0, ax); ay = fmaf(v0.y, c0, ay);
        az = fmaf(v0.z, c0, az); aw = fmaf(v0.w, c0, aw);
        ax = fmaf(v1.x, c1, ax); ay = fmaf(v1.y, c1, ay);
        az = fmaf(v1.z, c1, az); aw = fmaf(v1.w, c1, aw);
        ax = fmaf(v2.x, c2, ax); ay = fmaf(v2.y, c2, ay);
        az = fmaf(v2.z, c2, az); aw = fmaf(v2.w, c2, aw);
        ax = fmaf(v3.x, c3, ax); ay = fmaf(v3.y, c3, ay);
        az = fmaf(v3.z, c3, az); aw = fmaf(v3.w, c3, aw);
    }
    for (; e < e1; e++) {
        int s = __ldg(csr + e);
        float sc = __ldg(&g_mem[so + s]);
        float4 v = *reinterpret_cast<const float4*>(X + (size_t)s * DFEAT + lane * 4);
        ax = fmaf(v.x, sc, ax); ay = fmaf(v.y, sc, ay);
        az = fmaf(v.z, sc, az); aw = fmaf(v.w, sc, aw);
    }
    float s_in = __ldg(&g_mem[si + node]);
    float v0 = ax * s_in, v1 = ay * s_in, v2 = az * s_in, v3 = aw * s_in;
    __nv_bfloat16 h0, h1, h2, h3, l0, l1, l2, l3;
    split_bf16(v0, h0, l0);
    split_bf16(v1, h1, l1);
    split_bf16(v2, h2, l2);
    split_bf16(v3, h3, l3);
    uint4 o;
    o.x = pack2(h0, h1);  // slot 2*lane   hi
    o.y = pack2(l0, l1);  // slot 2*lane   lo
    o.z = pack2(h2, h3);  // slot 2*lane+1 hi
    o.w = pack2(l2, l3);  // slot 2*lane+1 lo
    *(reinterpret_cast<uint4*>(g_mem + oo) + (size_t)node * 32 + lane) = o;
}

// ---------------------------------------------------------------------------
// weight conversion / fusion
// ---------------------------------------------------------------------------
__global__ void wcvt_kernel(const float* __restrict__ Wa, const float* __restrict__ Wb) {
    int i = blockIdx.x * blockDim.x + threadIdx.x;  // 0..32767
    int sel = i >> 14, j = i & 16383;
    float v = sel ? __ldg(Wb + j) : __ldg(Wa + j);
    __nv_bfloat16 h, l;
    split_bf16(v, h, l);
    __nv_bfloat16* hi = reinterpret_cast<__nv_bfloat16*>(g_mem + (sel ? WB_W1R1_HI : WB_W1R0_HI));
    __nv_bfloat16* lo = reinterpret_cast<__nv_bfloat16*>(g_mem + (sel ? WB_W1R1_LO : WB_W1R0_LO));
    hi[j] = h;
    lo[j] = l;
}

__global__ void fuse_w_kernel(const float* __restrict__ W2, const float* __restrict__ Wm1p,
                              long long hi_off, long long lo_off) {
    int j = threadIdx.x;
    int k = blockIdx.x;
    float acc = 0.f;
#pragma unroll 4
    for (int t = 0; t < 128; t++)
        acc = fmaf(__ldg(W2 + k * 128 + t), __ldg(Wm1p + t * 128 + j), acc);
    __nv_bfloat16 h, l;
    split_bf16(acc, h, l);
    reinterpret_cast<__nv_bfloat16*>(g_mem + hi_off)[k * 128 + j] = h;
    reinterpret_cast<__nv_bfloat16*>(g_mem + lo_off)[k * 128 + j] = l;
}

__global__ void fuse_b_kernel(const float* __restrict__ b2r1, const float* __restrict__ b2r0,
                              const float* __restrict__ Wm1, float* __restrict__ bf) {
    int j = threadIdx.x;
    float acc = 0.f;
    for (int k = 0; k < 128; k++) {
        acc = fmaf(b2r1[k], Wm1[k * 128 + j], acc);
        acc = fmaf(b2r0[k], Wm1[(128 + k) * 128 + j], acc);
    }
    bf[j] = acc;
}

// ---------------------------------------------------------------------------
// mma helpers
// ---------------------------------------------------------------------------
__device__ __forceinline__ uint32_t smem_u32(const void* p) {
    uint32_t a;
    asm("{ .reg .u64 t; cvta.to.shared.u64 t, %1; cvt.u32.u64 %0, t; }" : "=r"(a) : "l"(p));
    return a;
}
__device__ __forceinline__ void ldsm_x4_t(uint32_t addr, uint32_t* r) {
    asm volatile("ldmatrix.sync.aligned.m8n8.x4.trans.shared.b16 {%0,%1,%2,%3}, [%4];"
                 : "=r"(r[0]), "=r"(r[1]), "=r"(r[2]), "=r"(r[3]) : "r"(addr));
}
__device__ __forceinline__ void mma16816(float* d, const uint32_t* a, const uint32_t* b) {
    asm volatile(
        "mma.sync.aligned.m16n8k16.row.col.f32.bf16.bf16.f32 "
        "{%0,%1,%2,%3}, {%4,%5,%6,%7}, {%8,%9}, {%0,%1,%2,%3};"
        : "+f"(d[0]), "+f"(d[1]), "+f"(d[2]), "+f"(d[3])
        : "r"(a[0]), "r"(a[1]), "r"(a[2]), "r"(a[3]), "r"(b[0]), "r"(b[1]));
}

// ---------------------------------------------------------------------------
// HMMA GEMM: A = pre-split pair-plane (uint2 {hi,lo}) loaded straight into
// fragments; B = pre-split bf16 planes -> padded smem -> ldmatrix.trans.
// Y[128/CTA,128] = sum_s relu?( X_s @ W_s ) + bias   (3-pass compensation)
// ---------------------------------------------------------------------------
#define BS_STRIDE 136
#define SM_BH 0
#define SM_BL 34816
#define SMEM_BYTES 69632

template <bool RELU>
__global__ void __launch_bounds__(256, 2) mma_gemm(
    const uint2* __restrict__ A0, const uint2* __restrict__ A1,
    const __nv_bfloat16* __restrict__ Wh0, const __nv_bfloat16* __restrict__ Wl0,
    const __nv_bfloat16* __restrict__ Wh1, const __nv_bfloat16* __restrict__ Wl1,
    const float* __restrict__ bias, float* __restrict__ Y,
    int M, int nsrc)
{
    extern __shared__ __align__(128) char smem[];
    uint32_t sb = smem_u32(smem);
    int tid = threadIdx.x;
    int wid = tid >> 5, lane = tid & 31;
    int row0 = blockIdx.x << 7;

    int wr = (wid & 3) * 32;   // warp row base
    int wc = (wid >> 2) * 64;  // warp col base
    int rr = wr + (lane >> 2); // fragment row (local)
    uint32_t b_k = lane & 15, b_c = (lane >> 4) * 8;

    float acc[2][8][4];
#pragma unroll
    for (int mi = 0; mi < 2; mi++)
#pragma unroll
        for (int ni = 0; ni < 8; ni++)
#pragma unroll
            for (int q = 0; q < 4; q++) acc[mi][ni][q] = 0.f;

    for (int s = 0; s < nsrc; s++) {
        if (s) __syncthreads();
        const uint2* A = s ? A1 : A0;
        const __nv_bfloat16* Wh = s ? Wh1 : Wh0;
        const __nv_bfloat16* Wl = s ? Wl1 : Wl0;

        // copy B hi/lo into padded smem (raw uint4 moves)
        for (int i = tid; i < 2048; i += 256) {
            int r = i >> 4, c = i & 15;
            uint32_t doff = (uint32_t)(r * BS_STRIDE + c * 8) * 2;
            *reinterpret_cast<uint4*>(smem + SM_BH + doff) =
                *reinterpret_cast<const uint4*>(Wh + r * 128 + c * 8);
            *reinterpret_cast<uint4*>(smem + SM_BL + doff) =
                *reinterpret_cast<const uint4*>(Wl + r * 128 + c * 8);
        }
        __syncthreads();

#pragma unroll
        for (int ks = 0; ks < 8; ks++) {
            int k0 = ks * 16;
            int kslot = (k0 >> 1) + (lane & 3);
            uint32_t ah[2][4], al[2][4];
#pragma unroll
            for (int mi = 0; mi < 2; mi++) {
                int r_ = row0 + rr + mi * 16;
                const uint2* bp = A + (size_t)r_ * 64 + kslot;
                uint2 z = make_uint2(0u, 0u);
                bool p0 = (r_ < M), p1 = (r_ + 8 < M);
                uint2 s0 = p0 ? __ldg(bp) : z;
                uint2 s1 = p1 ? __ldg(bp + 8 * 64) : z;
                uint2 s2 = p0 ? __ldg(bp + 4) : z;
                uint2 s3 = p1 ? __ldg(bp + 8 * 64 + 4) : z;
                ah[mi][0] = s0.x; al[mi][0] = s0.y;
                ah[mi][1] = s1.x; al[mi][1] = s1.y;
                ah[mi][2] = s2.x; al[mi][2] = s2.y;
                ah[mi][3] = s3.x; al[mi][3] = s3.y;
            }
#pragma unroll
            for (int nj = 0; nj < 4; nj++) {
                uint32_t boff = (uint32_t)((k0 + b_k) * BS_STRIDE + wc + nj * 16 + b_c) * 2;
                uint32_t bh[4], bl[4];
                ldsm_x4_t(sb + SM_BH + boff, bh);
                ldsm_x4_t(sb + SM_BL + boff, bl);
#pragma unroll
                for (int mi = 0; mi < 2; mi++) {
                    mma16816(acc[mi][nj * 2 + 0], ah[mi], &bh[0]);
                    mma16816(acc[mi][nj * 2 + 1], ah[mi], &bh[2]);
                    mma16816(acc[mi][nj * 2 + 0], ah[mi], &bl[0]);
                    mma16816(acc[mi][nj * 2 + 1], ah[mi], &bl[2]);
                    mma16816(acc[mi][nj * 2 + 0], al[mi], &bh[0]);
                    mma16816(acc[mi][nj * 2 + 1], al[mi], &bh[2]);
                }
            }
        }
    }

    // epilogue
    int gi = lane >> 2, qi = lane & 3;
#pragma unroll
    for (int mi = 0; mi < 2; mi++) {
#pragma unroll
        for (int half = 0; half < 2; half++) {
            int gr = row0 + wr + mi * 16 + gi + half * 8;
            if (gr >= M) continue;
            float* Yr = Y + (size_t)gr * DFEAT;
#pragma unroll
            for (int ni = 0; ni < 8; ni++) {
                int c = wc + ni * 8 + qi * 2;
                float2 bv = *reinterpret_cast<const float2*>(bias + c);
                float2 o;
                o.x = acc[mi][ni][half * 2 + 0] + bv.x;
                o.y = acc[mi][ni][half * 2 + 1] + bv.y;
                if (RELU) { o.x = fmaxf(o.x, 0.f); o.y = fmaxf(o.y, 0.f); }
                *reinterpret_cast<float2*>(Yr + c) = o;
            }
        }
    }
}

// ---------------------------------------------------------------------------
// BN column stats + head
// ---------------------------------------------------------------------------
__global__ void bn_stats_kernel(long long t_off, int M) {
    int c = threadIdx.x;
    int r0 = blockIdx.x * 128;
    int r1 = min(r0 + 128, M);
    const float* t = g_mem + t_off;
    float s = 0.f, s2 = 0.f;
    for (int i = r0; i < r1; i++) {
        float v = t[(size_t)i * DFEAT + c];
        s += v;
        s2 = fmaf(v, v, s2);
    }
    atomicAdd(&g_mem[OFF_STATS + c], s);
    atomicAdd(&g_mem[OFF_STATS + 128 + c], s2);
}

__global__ void bn_finalize_kernel(const float* __restrict__ gamma,
                                   const float* __restrict__ beta, int M) {
    int c = threadIdx.x;
    float inv_n = 1.0f / (float)M;
    float mu = g_mem[OFF_STATS + c] * inv_n;
    float var = g_mem[OFF_STATS + 128 + c] * inv_n - mu * mu;
    var = fmaxf(var, 0.f);
    float a = gamma[c] * rsqrtf(var + 1e-5f);
    g_mem[OFF_BN + c] = a;
    g_mem[OFF_BN + 128 + c] = beta[c] - mu * a;
}

__global__ void final_kernel(const float* __restrict__ Wm2, float* __restrict__ out, int M) {
    int gw = (int)(((long long)blockIdx.x * blockDim.x + threadIdx.x) >> 5);
    int lane = threadIdx.x & 31;
    if (gw >= M) return;
    int c = lane * 4;
    const float* trow = g_mem + OFF_T + (size_t)gw * DFEAT;
    float4 tv = *reinterpret_cast<const float4*>(trow + c);
    float4 av = *reinterpret_cast<const float4*>(g_mem + OFF_BN + c);
    float4 bv = *reinterpret_cast<const float4*>(g_mem + OFF_BN + 128 + c);
    float4 w0 = *reinterpret_cast<const float4*>(Wm2 + c * 2);
    float4 w1 = *reinterpret_cast<const float4*>(Wm2 + c * 2 + 4);
    float v0 = fmaxf(fmaf(tv.x, av.x, bv.x), 0.f);
    float v1 = fmaxf(fmaf(tv.y, av.y, bv.y), 0.f);
    float v2 = fmaxf(fmaf(tv.z, av.z, bv.z), 0.f);
    float v3 = fmaxf(fmaf(tv.w, av.w, bv.w), 0.f);
    float acc0 = v0 * w0.x + v1 * w0.z + v2 * w1.x + v3 * w1.z;
    float acc1 = v0 * w0.y + v1 * w0.w + v2 * w1.y + v3 * w1.w;
#pragma unroll
    for (int o = 16; o; o >>= 1) {
        acc0 += __shfl_xor_sync(0xFFFFFFFFu, acc0, o);
        acc1 += __shfl_xor_sync(0xFFFFFFFFu, acc1, o);
    }
    if (lane == 0) {
        out[(size_t)gw * 2 + 0] = acc0;
        out[(size_t)gw * 2 + 1] = acc1;
    }
}

// ---------------------------------------------------------------------------
// host
// ---------------------------------------------------------------------------
extern "C" void kernel_launch(void* const* d_in, const int* in_sizes, int n_in,
                              void* d_out, int out_size) {
    const float* xA   = (const float*)d_in[0];
    const float* xB   = (const float*)d_in[1];
    const int*   src0 = (const int*)d_in[2];
    const int*   dst0 = (const int*)d_in[3];
    const int*   src1 = (const int*)d_in[4];
    const int*   dst1 = (const int*)d_in[5];
    const float* W1r0 = (const float*)d_in[6];
    const float* b1r0 = (const float*)d_in[7];
    const float* W1r1 = (const float*)d_in[8];
    const float* b1r1 = (const float*)d_in[9];
    const float* W2r0 = (const float*)d_in[10];
    const float* b2r0 = (const float*)d_in[11];
    const float* W2r1 = (const float*)d_in[12];
    const float* b2r1 = (const float*)d_in[13];
    const float* Wm1  = (const float*)d_in[14];
    const float* gamma= (const float*)d_in[15];
    const float* beta = (const float*)d_in[16];
    const float* Wm2  = (const float*)d_in[17];
    float* out = (float*)d_out;

    int M  = in_sizes[0] / DFEAT;   // 50000
    int E0 = in_sizes[2];
    int E1 = in_sizes[4];

    float* gb = nullptr;
    cudaGetSymbolAddress((void**)&gb, g_mem);
    int* gip = reinterpret_cast<int*>(gb + OFF_INT);

    int* row0 = gip + I_ROW0;
    int* row1 = gip + I_ROW1;
    int* csr0 = gip + I_CSR0;
    int* csr1 = gip + I_CSR1;

    long long sOut0 = OFF_DEG;
    long long sIn0  = OFF_DEG + NNODES;
    long long sOut1 = OFF_DEG + 2LL * NNODES;
    long long sIn1  = OFF_DEG + 3LL * NNODES;

    cudaFuncSetAttribute(mma_gemm<true>, cudaFuncAttributeMaxDynamicSharedMemorySize, SMEM_BYTES);
    cudaFuncSetAttribute(mma_gemm<false>, cudaFuncAttributeMaxDynamicSharedMemorySize, SMEM_BYTES);

    const __nv_bfloat16* w1r0h = reinterpret_cast<const __nv_bfloat16*>(gb + WB_W1R0_HI);
    const __nv_bfloat16* w1r0l = reinterpret_cast<const __nv_bfloat16*>(gb + WB_W1R0_LO);
    const __nv_bfloat16* w1r1h = reinterpret_cast<const __nv_bfloat16*>(gb + WB_W1R1_HI);
    const __nv_bfloat16* w1r1l = reinterpret_cast<const __nv_bfloat16*>(gb + WB_W1R1_LO);
    const __nv_bfloat16* wfah  = reinterpret_cast<const __nv_bfloat16*>(gb + WB_WFA_HI);
    const __nv_bfloat16* wfal  = reinterpret_cast<const __nv_bfloat16*>(gb + WB_WFA_LO);
    const __nv_bfloat16* wfbh  = reinterpret_cast<const __nv_bfloat16*>(gb + WB_WFB_HI);
    const __nv_bfloat16* wfbl  = reinterpret_cast<const __nv_bfloat16*>(gb + WB_WFB_LO);
    const uint2* aggA = reinterpret_cast<const uint2*>(gb + OFF_AGGA);
    const uint2* aggB = reinterpret_cast<const uint2*>(gb + OFF_AGGB);

    int EA = E0 + E1;
    int gat_grid = (2 * NNODES * 32 + 255) / 256;
    int gemm_grid = (M + 127) / 128;

    // --- CSR build + scales ---
    zero2_kernel<<<128, 256>>>();
    count_all_kernel<<<(EA + 255) / 256, 256>>>(src0, dst0, src1, dst1, gip + I_CNT, E0, E1);
    scan_sums_kernel<<<2 * NCHUNK, 256>>>(gip);
    scan_offsets_kernel<<<1, 512>>>(gip);
    scan_expand_kernel<<<2 * NCHUNK, 256>>>(gip);
    fill_all_kernel<<<(EA + 255) / 256, 256>>>(src0, dst0, src1, dst1, gip, E0, E1);

    // --- weight prep (graph-independent) ---
    wcvt_kernel<<<128, 256>>>(W1r0, W1r1);
    fuse_w_kernel<<<128, 128>>>(W2r1, Wm1, WB_WFA_HI, WB_WFA_LO);
    fuse_w_kernel<<<128, 128>>>(W2r0, Wm1 + 128 * 128, WB_WFB_HI, WB_WFB_LO);
    fuse_b_kernel<<<1, 128>>>(b2r1, b2r0, Wm1, gb + OFF_BF);

    // --- conv1: merged gather (r0: xA->aggB, r1: xB->aggA) + 2 GEMMs ---
    gather2_kernel<<<gat_grid, 256>>>(xA, xB, 0, 0, row0, csr0, row1, csr1,
                                      sOut0, sIn0, OFF_AGGB,
                                      sOut1, sIn1, OFF_AGGA);
    mma_gemm<true><<<gemm_grid, 256, SMEM_BYTES>>>(
        aggB, nullptr, w1r0h, w1r0l, nullptr, nullptr, b1r0, gb + OFF_HB, M, 1);
    mma_gemm<true><<<gemm_grid, 256, SMEM_BYTES>>>(
        aggA, nullptr, w1r1h, w1r1l, nullptr, nullptr, b1r1, gb + OFF_HA, M, 1);

    // --- conv2: merged gather (r0: HA->aggB, r1: HB->aggA) ---
    gather2_kernel<<<gat_grid, 256>>>(nullptr, nullptr, OFF_HA, OFF_HB,
                                      row0, csr0, row1, csr1,
                                      sOut0, sIn0, OFF_AGGB,
                                      sOut1, sIn1, OFF_AGGA);

    // --- fused conv2+MLP GEMM: t = aggA@WfA + aggB@WfB + bf ---
    mma_gemm<false><<<gemm_grid, 256, SMEM_BYTES>>>(
        aggA, aggB, wfah, wfal, wfbh, wfbl, gb + OFF_BF, gb + OFF_T, M, 2);

    // --- BN + head ---
    bn_stats_kernel<<<(M + 127) / 128, 128>>>(OFF_T, M);
    bn_finalize_kernel<<<1, 128>>>(gamma, beta, M);
    final_kernel<<<(M + 7) / 8, 256>>>(Wm2, out, M);
}

// round 16
// speedup vs baseline: 2.0037x; 1.1093x over previous
#include <cuda_runtime.h>
#include <cuda_bf16.h>
#include <cstdint>

// ---------------------------------------------------------------------------
// RGCN2 on GB300 (sm_103): CSR gather emitting bf16 hi/lo pair-planes +
// HMMA GEMMs (pre-split A/B) + fused conv2+MLP + fused BN stats epilogue.
// ---------------------------------------------------------------------------

#define NNODES 50000
#define DFEAT 128
#define NCHUNK 196   // ceil(NNODES/256)

static const long long OFF_DEG   = 0;                        // 4*N rsqrt scales (float)
static const long long OFF_STATS = 4LL * NNODES;             // 256
static const long long OFF_BN    = OFF_STATS + 256;          // 256 (unused spare)
static const long long SZ        = (long long)NNODES * DFEAT;
static const long long OFF_AGGA  = OFF_BN + 256;             // pair-plane {hi,lo} uint2
static const long long OFF_AGGB  = OFF_AGGA + SZ;            // pair-plane
static const long long OFF_HA    = OFF_AGGB + SZ;            // fp32
static const long long OFF_HB    = OFF_HA + SZ;              // fp32
static const long long OFF_T     = OFF_HB + SZ;              // fp32
static const long long OFF_WB    = OFF_T + SZ;               // bf16 weight planes
static const long long OFF_BF    = OFF_WB + 65536;           // fused bias (128)
static const long long OFF_INT   = OFF_BF + 128;

static const long long WB_W1R0_HI = OFF_WB + 0;
static const long long WB_W1R0_LO = OFF_WB + 8192;
static const long long WB_W1R1_HI = OFF_WB + 16384;
static const long long WB_W1R1_LO = OFF_WB + 24576;
static const long long WB_WFA_HI  = OFF_WB + 32768;
static const long long WB_WFA_LO  = OFF_WB + 40960;
static const long long WB_WFB_HI  = OFF_WB + 49152;
static const long long WB_WFB_LO  = OFF_WB + 57344;

static const long long I_CNT  = 0;                    // 4*N
static const long long I_ROW0 = 4LL * NNODES;
static const long long I_ROW1 = I_ROW0 + NNODES + 1;
static const long long I_CUR0 = I_ROW1 + NNODES + 1;
static const long long I_CUR1 = I_CUR0 + NNODES;
static const long long I_CSR0 = I_CUR1 + NNODES;
static const long long I_CSR1 = I_CSR0 + 600000;
static const long long I_PART = I_CSR1 + 600000;      // 2*NCHUNK chunk partials

__device__ float g_mem[33900000];

__device__ __forceinline__ void split_bf16(float v, __nv_bfloat16& h, __nv_bfloat16& l) {
    h = __float2bfloat16(v);
    l = __float2bfloat16(v - __bfloat162float(h));
}
__device__ __forceinline__ uint32_t pack2(__nv_bfloat16 a, __nv_bfloat16 b) {
    return ((uint32_t)__bfloat16_as_ushort(b) << 16) | __bfloat16_as_ushort(a);
}

// ---------------------------------------------------------------------------
// setup kernels
// ---------------------------------------------------------------------------
__global__ void zero2_kernel() {
    long long i = (long long)blockIdx.x * blockDim.x + threadIdx.x;
    long long stride = (long long)gridDim.x * blockDim.x;
    float4* p = reinterpret_cast<float4*>(g_mem + OFF_INT);
    for (long long j = i; j < NNODES; j += stride) p[j] = make_float4(0.f, 0.f, 0.f, 0.f);
    if (i < 64) reinterpret_cast<float4*>(g_mem + OFF_STATS)[i] = make_float4(0.f, 0.f, 0.f, 0.f);
}

__global__ void count_all_kernel(const int* __restrict__ src0, const int* __restrict__ dst0,
                                 const int* __restrict__ src1, const int* __restrict__ dst1,
                                 int* __restrict__ cnt, int E0, int E1) {
    int e = blockIdx.x * blockDim.x + threadIdx.x;
    if (e < E0) {
        atomicAdd(&cnt[src0[e]], 1);
        atomicAdd(&cnt[NNODES + dst0[e]], 1);
    } else if (e < E0 + E1) {
        int t = e - E0;
        atomicAdd(&cnt[2 * NNODES + src1[t]], 1);
        atomicAdd(&cnt[3 * NNODES + dst1[t]], 1);
    }
}

// grid = 2*NCHUNK: per-chunk in-degree sums; plus grid-stride rsqrt of all 4N counts
__global__ void __launch_bounds__(256) scan_sums_kernel(int* __restrict__ gi) {
    __shared__ int ws[8];
    int b = blockIdx.x, tid = threadIdx.x;
    int rel = b / NCHUNK, c = b % NCHUNK;
    const int* cnt = gi + I_CNT + (rel ? 3 : 1) * (long long)NNODES;
    int i = c * 256 + tid;
    int v = (i < NNODES) ? cnt[i] : 0;
    int x = v;
#pragma unroll
    for (int o = 16; o; o >>= 1) x += __shfl_down_sync(0xFFFFFFFFu, x, o);
    if ((tid & 31) == 0) ws[tid >> 5] = x;
    __syncthreads();
    if (tid == 0) {
        int s = 0;
#pragma unroll
        for (int w = 0; w < 8; w++) s += ws[w];
        gi[I_PART + b] = s;
    }
    const int* call = gi + I_CNT;
    for (long long j = (long long)b * 256 + tid; j < 4LL * NNODES; j += 2LL * NCHUNK * 256)
        g_mem[OFF_DEG + j] = rsqrtf(fmaxf((float)call[j], 1.0f));
}

// grid = 2*NCHUNK: in-block chunk-offset reduction + block scan -> row, cur (+row[N])
__global__ void __launch_bounds__(256) scan_expand_kernel(int* __restrict__ gi) {
    __shared__ int red[8];
    __shared__ int ws[8];
    int b = blockIdx.x, tid = threadIdx.x;
    int lane = tid & 31, w = tid >> 5;
    int rel = b / NCHUNK, c = b % NCHUNK;
    const int* cnt = gi + I_CNT + (rel ? 3 : 1) * (long long)NNODES;
    int* row = gi + (rel ? I_ROW1 : I_ROW0);
    int* cur = gi + (rel ? I_CUR1 : I_CUR0);

    // offset = sum of partials of chunks < c (this relation)
    int pv = (tid < c) ? gi[I_PART + rel * NCHUNK + tid] : 0;
#pragma unroll
    for (int o = 16; o; o >>= 1) pv += __shfl_down_sync(0xFFFFFFFFu, pv, o);
    if (lane == 0) red[w] = pv;
    __syncthreads();
    int offset = red[0] + red[1] + red[2] + red[3] + red[4] + red[5] + red[6] + red[7];
    __syncthreads();

    int i = c * 256 + tid;
    int v = (i < NNODES) ? cnt[i] : 0;
    int x = v;
#pragma unroll
    for (int o = 1; o < 32; o <<= 1) {
        int y = __shfl_up_sync(0xFFFFFFFFu, x, o);
        if (lane >= o) x += y;
    }
    if (lane == 31) ws[w] = x;
    __syncthreads();
    if (w == 0) {
        int t = (lane < 8) ? ws[lane] : 0;
#pragma unroll
        for (int o = 1; o < 8; o <<= 1) {
            int y = __shfl_up_sync(0xFFFFFFFFu, t, o);
            if (lane >= o) t += y;
        }
        if (lane < 8) ws[lane] = t;
    }
    __syncthreads();
    int excl = x - v + (w ? ws[w - 1] : 0) + offset;
    if (i < NNODES) {
        row[i] = excl;
        cur[i] = excl;
    }
    if (c == NCHUNK - 1 && tid == 0) row[NNODES] = offset + ws[7];
}

__global__ void fill_all_kernel(const int* __restrict__ src0, const int* __restrict__ dst0,
                                const int* __restrict__ src1, const int* __restrict__ dst1,
                                int* __restrict__ gi, int E0, int E1) {
    int e = blockIdx.x * blockDim.x + threadIdx.x;
    if (e < E0) {
        int p = atomicAdd(&gi[I_CUR0 + dst0[e]], 1);
        gi[I_CSR0 + p] = src0[e];
    } else if (e < E0 + E1) {
        int t = e - E0;
        int p = atomicAdd(&gi[I_CUR1 + dst1[t]], 1);
        gi[I_CSR1 + p] = src1[t];
    }
}

// merged gather (both relations): out pair-plane {hi,lo} uint2 slots.
__global__ void gather2_kernel(const float* __restrict__ X0g, const float* __restrict__ X1g,
                               long long x0_off, long long x1_off,
                               const int* __restrict__ row0, const int* __restrict__ csr0,
                               const int* __restrict__ row1, const int* __restrict__ csr1,
                               long long so0, long long si0, long long out0,
                               long long so1, long long si1, long long out1) {
    int gw = (int)(((long long)blockIdx.x * blockDim.x + threadIdx.x) >> 5);
    int lane = threadIdx.x & 31;
    if (gw >= 2 * NNODES) return;
    int rel = (gw >= NNODES);
    int node = gw - (rel ? NNODES : 0);
    const int* row = rel ? row1 : row0;
    const int* csr = rel ? csr1 : csr0;
    const float* Xg = rel ? X1g : X0g;
    const float* X = Xg ? Xg : (g_mem + (rel ? x1_off : x0_off));
    long long so = rel ? so1 : so0;
    long long si = rel ? si1 : si0;
    long long oo = rel ? out1 : out0;

    int e0 = __ldg(row + node), e1 = __ldg(row + node + 1);
    float ax = 0.f, ay = 0.f, az = 0.f, aw = 0.f;
    int e = e0;
    for (; e + 4 <= e1; e += 4) {
        int s0 = __ldg(csr + e), s1 = __ldg(csr + e + 1);
        int s2 = __ldg(csr + e + 2), s3 = __ldg(csr + e + 3);
        float c0 = __ldg(&g_mem[so + s0]);
        float c1 = __ldg(&g_mem[so + s1]);
        float c2 = __ldg(&g_mem[so + s2]);
        float c3 = __ldg(&g_mem[so + s3]);
        float4 v0 = *reinterpret_cast<const float4*>(X + (size_t)s0 * DFEAT + lane * 4);
        float4 v1 = *reinterpret_cast<const float4*>(X + (size_t)s1 * DFEAT + lane * 4);
        float4 v2 = *reinterpret_cast<const float4*>(X + (size_t)s2 * DFEAT + lane * 4);
        float4 v3 = *reinterpret_cast<const float4*>(X + (size_t)s3 * DFEAT + lane * 4);
        ax = fmaf(v0.x, c0, ax); ay = fmaf(v0.y, c0, ay);
        az = fmaf(v0.z, c0, az); aw = fmaf(v0.w, c0, aw);
        ax = fmaf(v1.x, c1, ax); ay = fmaf(v1.y, c1, ay);
        az = fmaf(v1.z, c1, az); aw = fmaf(v1.w, c1, aw);
        ax = fmaf(v2.x, c2, ax); ay = fmaf(v2.y, c2, ay);
        az = fmaf(v2.z, c2, az); aw = fmaf(v2.w, c2, aw);
        ax = fmaf(v3.x, c3, ax); ay = fmaf(v3.y, c3, ay);
        az = fmaf(v3.z, c3, az); aw = fmaf(v3.w, c3, aw);
    }
    for (; e < e1; e++) {
        int s = __ldg(csr + e);
        float sc = __ldg(&g_mem[so + s]);
        float4 v = *reinterpret_cast<const float4*>(X + (size_t)s * DFEAT + lane * 4);
        ax = fmaf(v.x, sc, ax); ay = fmaf(v.y, sc, ay);
        az = fmaf(v.z, sc, az); aw = fmaf(v.w, sc, aw);
    }
    float s_in = __ldg(&g_mem[si + node]);
    float v0 = ax * s_in, v1 = ay * s_in, v2 = az * s_in, v3 = aw * s_in;
    __nv_bfloat16 h0, h1, h2, h3, l0, l1, l2, l3;
    split_bf16(v0, h0, l0);
    split_bf16(v1, h1, l1);
    split_bf16(v2, h2, l2);
    split_bf16(v3, h3, l3);
    uint4 o;
    o.x = pack2(h0, h1);
    o.y = pack2(l0, l1);
    o.z = pack2(h2, h3);
    o.w = pack2(l2, l3);
    *(reinterpret_cast<uint4*>(g_mem + oo) + (size_t)node * 32 + lane) = o;
}

// ---------------------------------------------------------------------------
// merged weight prep: blocks 0-127 fuse WFA; 128-255 fuse WFB; 256-383 wcvt;
// block 384 fused bias.  128 threads/block.
// ---------------------------------------------------------------------------
__global__ void __launch_bounds__(128) wprep_kernel(
    const float* __restrict__ W1r0, const float* __restrict__ W1r1,
    const float* __restrict__ W2r0, const float* __restrict__ W2r1,
    const float* __restrict__ Wm1,
    const float* __restrict__ b2r0, const float* __restrict__ b2r1,
    float* __restrict__ bf) {
    int b = blockIdx.x, j = threadIdx.x;
    if (b < 256) {
        int k = b & 127;
        const float* W2 = (b < 128) ? W2r1 : W2r0;
        const float* Wp = (b < 128) ? Wm1 : (Wm1 + 128 * 128);
        long long hi_off = (b < 128) ? WB_WFA_HI : WB_WFB_HI;
        long long lo_off = (b < 128) ? WB_WFA_LO : WB_WFB_LO;
        float acc = 0.f;
#pragma unroll 4
        for (int t = 0; t < 128; t++)
            acc = fmaf(__ldg(W2 + k * 128 + t), __ldg(Wp + t * 128 + j), acc);
        __nv_bfloat16 h, l;
        split_bf16(acc, h, l);
        reinterpret_cast<__nv_bfloat16*>(g_mem + hi_off)[k * 128 + j] = h;
        reinterpret_cast<__nv_bfloat16*>(g_mem + lo_off)[k * 128 + j] = l;
    } else if (b < 384) {
        int idx = (b - 256) * 128 + j;  // 0..16383
        __nv_bfloat16 h, l;
        split_bf16(__ldg(W1r0 + idx), h, l);
        reinterpret_cast<__nv_bfloat16*>(g_mem + WB_W1R0_HI)[idx] = h;
        reinterpret_cast<__nv_bfloat16*>(g_mem + WB_W1R0_LO)[idx] = l;
        split_bf16(__ldg(W1r1 + idx), h, l);
        reinterpret_cast<__nv_bfloat16*>(g_mem + WB_W1R1_HI)[idx] = h;
        reinterpret_cast<__nv_bfloat16*>(g_mem + WB_W1R1_LO)[idx] = l;
    } else {
        float acc = 0.f;
        for (int k = 0; k < 128; k++) {
            acc = fmaf(__ldg(b2r1 + k), __ldg(Wm1 + k * 128 + j), acc);
            acc = fmaf(__ldg(b2r0 + k), __ldg(Wm1 + (128 + k) * 128 + j), acc);
        }
        bf[j] = acc;
    }
}

// ---------------------------------------------------------------------------
// mma helpers
// ---------------------------------------------------------------------------
__device__ __forceinline__ uint32_t smem_u32(const void* p) {
    uint32_t a;
    asm("{ .reg .u64 t; cvta.to.shared.u64 t, %1; cvt.u32.u64 %0, t; }" : "=r"(a) : "l"(p));
    return a;
}
__device__ __forceinline__ void ldsm_x4_t(uint32_t addr, uint32_t* r) {
    asm volatile("ldmatrix.sync.aligned.m8n8.x4.trans.shared.b16 {%0,%1,%2,%3}, [%4];"
                 : "=r"(r[0]), "=r"(r[1]), "=r"(r[2]), "=r"(r[3]) : "r"(addr));
}
__device__ __forceinline__ void mma16816(float* d, const uint32_t* a, const uint32_t* b) {
    asm volatile(
        "mma.sync.aligned.m16n8k16.row.col.f32.bf16.bf16.f32 "
        "{%0,%1,%2,%3}, {%4,%5,%6,%7}, {%8,%9}, {%0,%1,%2,%3};"
        : "+f"(d[0]), "+f"(d[1]), "+f"(d[2]), "+f"(d[3])
        : "r"(a[0]), "r"(a[1]), "r"(a[2]), "r"(a[3]), "r"(b[0]), "r"(b[1]));
}

#define BS_STRIDE 136
#define SM_BH 0
#define SM_BL 34816
#define SMEM_BYTES 69632

// shared mainloop body: accumulates one source (A pair-plane @ B planes)
template <typename F>
__device__ __forceinline__ void gemm_source(
    const uint2* __restrict__ A, const __nv_bfloat16* __restrict__ Wh,
    const __nv_bfloat16* __restrict__ Wl, char* smem, uint32_t sb,
    int tid, int lane, int row0, int rr, uint32_t b_k, uint32_t b_c, int wc,
    int M, float acc[2][8][4]) {
    // copy B hi/lo into padded smem
    for (int i = tid; i < 2048; i += 256) {
        int r = i >> 4, c = i & 15;
        uint32_t doff = (uint32_t)(r * BS_STRIDE + c * 8) * 2;
        *reinterpret_cast<uint4*>(smem + SM_BH + doff) =
            *reinterpret_cast<const uint4*>(Wh + r * 128 + c * 8);
        *reinterpret_cast<uint4*>(smem + SM_BL + doff) =
            *reinterpret_cast<const uint4*>(Wl + r * 128 + c * 8);
    }
    __syncthreads();

#pragma unroll
    for (int ks = 0; ks < 8; ks++) {
        int k0 = ks * 16;
        int kslot = (k0 >> 1) + (lane & 3);
        uint32_t ah[2][4], al[2][4];
#pragma unroll
        for (int mi = 0; mi < 2; mi++) {
            int r_ = row0 + rr + mi * 16;
            const uint2* bp = A + (size_t)r_ * 64 + kslot;
            uint2 z = make_uint2(0u, 0u);
            bool p0 = (r_ < M), p1 = (r_ + 8 < M);
            uint2 s0 = p0 ? __ldg(bp) : z;
            uint2 s1 = p1 ? __ldg(bp + 8 * 64) : z;
            uint2 s2 = p0 ? __ldg(bp + 4) : z;
            uint2 s3 = p1 ? __ldg(bp + 8 * 64 + 4) : z;
            ah[mi][0] = s0.x; al[mi][0] = s0.y;
            ah[mi][1] = s1.x; al[mi][1] = s1.y;
            ah[mi][2] = s2.x; al[mi][2] = s2.y;
            ah[mi][3] = s3.x; al[mi][3] = s3.y;
        }
#pragma unroll
        for (int nj = 0; nj < 4; nj++) {
            uint32_t boff = (uint32_t)((k0 + b_k) * BS_STRIDE + wc + nj * 16 + b_c) * 2;
            uint32_t bh[4], bl[4];
            ldsm_x4_t(sb + SM_BH + boff, bh);
            ldsm_x4_t(sb + SM_BL + boff, bl);
#pragma unroll
            for (int mi = 0; mi < 2; mi++) {
                mma16816(acc[mi][nj * 2 + 0], ah[mi], &bh[0]);
                mma16816(acc[mi][nj * 2 + 1], ah[mi], &bh[2]);
                mma16816(acc[mi][nj * 2 + 0], ah[mi], &bl[0]);
                mma16816(acc[mi][nj * 2 + 1], ah[mi], &bl[2]);
                mma16816(acc[mi][nj * 2 + 0], al[mi], &bh[0]);
                mma16816(acc[mi][nj * 2 + 1], al[mi], &bh[2]);
            }
        }
    }
}

// conv1: both relations in one launch (blockIdx.y = job), relu epilogue
__global__ void __launch_bounds__(256, 2) mma_gemm_dual(
    const uint2* __restrict__ Aa, const uint2* __restrict__ Ab,
    const __nv_bfloat16* __restrict__ Wha, const __nv_bfloat16* __restrict__ Wla,
    const __nv_bfloat16* __restrict__ Whb, const __nv_bfloat16* __restrict__ Wlb,
    const float* __restrict__ biasa, const float* __restrict__ biasb,
    float* __restrict__ Ya, float* __restrict__ Yb, int M) {
    extern __shared__ __align__(128) char smem[];
    uint32_t sb = smem_u32(smem);
    int job = blockIdx.y;
    const uint2* A = job ? Ab : Aa;
    const __nv_bfloat16* Wh = job ? Whb : Wha;
    const __nv_bfloat16* Wl = job ? Wlb : Wla;
    const float* bias = job ? biasb : biasa;
    float* Y = job ? Yb : Ya;

    int tid = threadIdx.x;
    int wid = tid >> 5, lane = tid & 31;
    int row0 = blockIdx.x << 7;
    int wr = (wid & 3) * 32;
    int wc = (wid >> 2) * 64;
    int rr = wr + (lane >> 2);
    uint32_t b_k = lane & 15, b_c = (lane >> 4) * 8;

    float acc[2][8][4];
#pragma unroll
    for (int mi = 0; mi < 2; mi++)
#pragma unroll
        for (int ni = 0; ni < 8; ni++)
#pragma unroll
            for (int q = 0; q < 4; q++) acc[mi][ni][q] = 0.f;

    gemm_source<int>(A, Wh, Wl, smem, sb, tid, lane, row0, rr, b_k, b_c, wc, M, acc);

    int gi = lane >> 2, qi = lane & 3;
#pragma unroll
    for (int mi = 0; mi < 2; mi++)
#pragma unroll
        for (int half = 0; half < 2; half++) {
            int gr = row0 + wr + mi * 16 + gi + half * 8;
            if (gr >= M) continue;
            float* Yr = Y + (size_t)gr * DFEAT;
#pragma unroll
            for (int ni = 0; ni < 8; ni++) {
                int c = wc + ni * 8 + qi * 2;
                float2 bv = *reinterpret_cast<const float2*>(bias + c);
                float2 o;
                o.x = fmaxf(acc[mi][ni][half * 2 + 0] + bv.x, 0.f);
                o.y = fmaxf(acc[mi][ni][half * 2 + 1] + bv.y, 0.f);
                *reinterpret_cast<float2*>(Yr + c) = o;
            }
        }
}

// fused conv2+MLP GEMM (2 sources) + BN stats epilogue (column sums into g_stats)
__global__ void __launch_bounds__(256, 2) mma_gemm_fused(
    const uint2* __restrict__ A0, const uint2* __restrict__ A1,
    const __nv_bfloat16* __restrict__ Wh0, const __nv_bfloat16* __restrict__ Wl0,
    const __nv_bfloat16* __restrict__ Wh1, const __nv_bfloat16* __restrict__ Wl1,
    const float* __restrict__ bias, float* __restrict__ Y,
    float* __restrict__ stats, int M) {
    extern __shared__ __align__(128) char smem[];
    uint32_t sb = smem_u32(smem);
    int tid = threadIdx.x;
    int wid = tid >> 5, lane = tid & 31;
    int row0 = blockIdx.x << 7;
    int wr = (wid & 3) * 32;
    int wc = (wid >> 2) * 64;
    int rr = wr + (lane >> 2);
    uint32_t b_k = lane & 15, b_c = (lane >> 4) * 8;

    float acc[2][8][4];
#pragma unroll
    for (int mi = 0; mi < 2; mi++)
#pragma unroll
        for (int ni = 0; ni < 8; ni++)
#pragma unroll
            for (int q = 0; q < 4; q++) acc[mi][ni][q] = 0.f;

    gemm_source<int>(A0, Wh0, Wl0, smem, sb, tid, lane, row0, rr, b_k, b_c, wc, M, acc);
    __syncthreads();
    gemm_source<int>(A1, Wh1, Wl1, smem, sb, tid, lane, row0, rr, b_k, b_c, wc, M, acc);

    // B smem no longer needed: reuse front 256 floats for block stats
    __syncthreads();
    float* ssum = reinterpret_cast<float*>(smem);
    if (tid < 256) ssum[tid] = 0.f;
    __syncthreads();

    int gi = lane >> 2, qi = lane & 3;
    float ls[16], ls2[16];
#pragma unroll
    for (int k = 0; k < 16; k++) { ls[k] = 0.f; ls2[k] = 0.f; }

#pragma unroll
    for (int mi = 0; mi < 2; mi++)
#pragma unroll
        for (int half = 0; half < 2; half++) {
            int gr = row0 + wr + mi * 16 + gi + half * 8;
            if (gr >= M) continue;
            float* Yr = Y + (size_t)gr * DFEAT;
#pragma unroll
            for (int ni = 0; ni < 8; ni++) {
                int c = wc + ni * 8 + qi * 2;
                float2 bv = *reinterpret_cast<const float2*>(bias + c);
                float2 o;
                o.x = acc[mi][ni][half * 2 + 0] + bv.x;
                o.y = acc[mi][ni][half * 2 + 1] + bv.y;
                *reinterpret_cast<float2*>(Yr + c) = o;
                ls[ni * 2 + 0] += o.x;
                ls2[ni * 2 + 0] = fmaf(o.x, o.x, ls2[ni * 2 + 0]);
                ls[ni * 2 + 1] += o.y;
                ls2[ni * 2 + 1] = fmaf(o.y, o.y, ls2[ni * 2 + 1]);
            }
        }

    // reduce over gi (lane bits 2..4), then smem atomics from gi==0 lanes
#pragma unroll
    for (int k = 0; k < 16; k++) {
#pragma unroll
        for (int off = 4; off <= 16; off <<= 1) {
            ls[k] += __shfl_xor_sync(0xFFFFFFFFu, ls[k], off);
            ls2[k] += __shfl_xor_sync(0xFFFFFFFFu, ls2[k], off);
        }
    }
    if (gi == 0) {
#pragma unroll
        for (int ni = 0; ni < 8; ni++) {
            int c = wc + ni * 8 + qi * 2;
            atomicAdd(&ssum[c], ls[ni * 2 + 0]);
            atomicAdd(&ssum[c + 1], ls[ni * 2 + 1]);
            atomicAdd(&ssum[128 + c], ls2[ni * 2 + 0]);
            atomicAdd(&ssum[128 + c + 1], ls2[ni * 2 + 1]);
        }
    }
    __syncthreads();
    if (tid < 256) atomicAdd(&stats[tid], ssum[tid]);
}

// ---------------------------------------------------------------------------
// head: per-block BN finalize + normalize + relu + [128x2] GEMV
// ---------------------------------------------------------------------------
__global__ void final_kernel(const float* __restrict__ Wm2,
                             const float* __restrict__ gamma,
                             const float* __restrict__ beta,
                             float* __restrict__ out, int M) {
    __shared__ float sa[128], sbv[128];
    if (threadIdx.x < 128) {
        int c = threadIdx.x;
        float inv_n = 1.0f / (float)M;
        float mu = g_mem[OFF_STATS + c] * inv_n;
        float var = g_mem[OFF_STATS + 128 + c] * inv_n - mu * mu;
        var = fmaxf(var, 0.f);
        float a = __ldg(gamma + c) * rsqrtf(var + 1e-5f);
        sa[c] = a;
        sbv[c] = __ldg(beta + c) - mu * a;
    }
    __syncthreads();
    int gw = (int)(((long long)blockIdx.x * blockDim.x + threadIdx.x) >> 5);
    int lane = threadIdx.x & 31;
    if (gw >= M) return;
    int c = lane * 4;
    const float* trow = g_mem + OFF_T + (size_t)gw * DFEAT;
    float4 tv = *reinterpret_cast<const float4*>(trow + c);
    float4 av = *reinterpret_cast<const float4*>(&sa[c]);
    float4 bv = *reinterpret_cast<const float4*>(&sbv[c]);
    float4 w0 = *reinterpret_cast<const float4*>(Wm2 + c * 2);
    float4 w1 = *reinterpret_cast<const float4*>(Wm2 + c * 2 + 4);
    float v0 = fmaxf(fmaf(tv.x, av.x, bv.x), 0.f);
    float v1 = fmaxf(fmaf(tv.y, av.y, bv.y), 0.f);
    float v2 = fmaxf(fmaf(tv.z, av.z, bv.z), 0.f);
    float v3 = fmaxf(fmaf(tv.w, av.w, bv.w), 0.f);
    float acc0 = v0 * w0.x + v1 * w0.z + v2 * w1.x + v3 * w1.z;
    float acc1 = v0 * w0.y + v1 * w0.w + v2 * w1.y + v3 * w1.w;
#pragma unroll
    for (int o = 16; o; o >>= 1) {
        acc0 += __shfl_xor_sync(0xFFFFFFFFu, acc0, o);
        acc1 += __shfl_xor_sync(0xFFFFFFFFu, acc1, o);
    }
    if (lane == 0) {
        out[(size_t)gw * 2 + 0] = acc0;
        out[(size_t)gw * 2 + 1] = acc1;
    }
}

// ---------------------------------------------------------------------------
// host
// ---------------------------------------------------------------------------
extern "C" void kernel_launch(void* const* d_in, const int* in_sizes, int n_in,
                              void* d_out, int out_size) {
    const float* xA   = (const float*)d_in[0];
    const float* xB   = (const float*)d_in[1];
    const int*   src0 = (const int*)d_in[2];
    const int*   dst0 = (const int*)d_in[3];
    const int*   src1 = (const int*)d_in[4];
    const int*   dst1 = (const int*)d_in[5];
    const float* W1r0 = (const float*)d_in[6];
    const float* b1r0 = (const float*)d_in[7];
    const float* W1r1 = (const float*)d_in[8];
    const float* b1r1 = (const float*)d_in[9];
    const float* W2r0 = (const float*)d_in[10];
    const float* b2r0 = (const float*)d_in[11];
    const float* W2r1 = (const float*)d_in[12];
    const float* b2r1 = (const float*)d_in[13];
    const float* Wm1  = (const float*)d_in[14];
    const float* gamma= (const float*)d_in[15];
    const float* beta = (const float*)d_in[16];
    const float* Wm2  = (const float*)d_in[17];
    float* out = (float*)d_out;

    int M  = in_sizes[0] / DFEAT;   // 50000
    int E0 = in_sizes[2];
    int E1 = in_sizes[4];

    float* gb = nullptr;
    cudaGetSymbolAddress((void**)&gb, g_mem);
    int* gip = reinterpret_cast<int*>(gb + OFF_INT);

    int* row0 = gip + I_ROW0;
    int* row1 = gip + I_ROW1;
    int* csr0 = gip + I_CSR0;
    int* csr1 = gip + I_CSR1;

    long long sOut0 = OFF_DEG;
    long long sIn0  = OFF_DEG + NNODES;
    long long sOut1 = OFF_DEG + 2LL * NNODES;
    long long sIn1  = OFF_DEG + 3LL * NNODES;

    cudaFuncSetAttribute(mma_gemm_dual, cudaFuncAttributeMaxDynamicSharedMemorySize, SMEM_BYTES);
    cudaFuncSetAttribute(mma_gemm_fused, cudaFuncAttributeMaxDynamicSharedMemorySize, SMEM_BYTES);

    const __nv_bfloat16* w1r0h = reinterpret_cast<const __nv_bfloat16*>(gb + WB_W1R0_HI);
    const __nv_bfloat16* w1r0l = reinterpret_cast<const __nv_bfloat16*>(gb + WB_W1R0_LO);
    const __nv_bfloat16* w1r1h = reinterpret_cast<const __nv_bfloat16*>(gb + WB_W1R1_HI);
    const __nv_bfloat16* w1r1l = reinterpret_cast<const __nv_bfloat16*>(gb + WB_W1R1_LO);
    const __nv_bfloat16* wfah  = reinterpret_cast<const __nv_bfloat16*>(gb + WB_WFA_HI);
    const __nv_bfloat16* wfal  = reinterpret_cast<const __nv_bfloat16*>(gb + WB_WFA_LO);
    const __nv_bfloat16* wfbh  = reinterpret_cast<const __nv_bfloat16*>(gb + WB_WFB_HI);
    const __nv_bfloat16* wfbl  = reinterpret_cast<const __nv_bfloat16*>(gb + WB_WFB_LO);
    const uint2* aggA = reinterpret_cast<const uint2*>(gb + OFF_AGGA);
    const uint2* aggB = reinterpret_cast<const uint2*>(gb + OFF_AGGB);

    int EA = E0 + E1;
    int gat_grid = (2 * NNODES * 32 + 255) / 256;
    int gemm_grid = (M + 127) / 128;

    // --- CSR build + scales (5 launches) ---
    zero2_kernel<<<128, 256>>>();
    count_all_kernel<<<(EA + 255) / 256, 256>>>(src0, dst0, src1, dst1, gip + I_CNT, E0, E1);
    scan_sums_kernel<<<2 * NCHUNK, 256>>>(gip);
    scan_expand_kernel<<<2 * NCHUNK, 256>>>(gip);
    fill_all_kernel<<<(EA + 255) / 256, 256>>>(src0, dst0, src1, dst1, gip, E0, E1);

    // --- merged weight prep ---
    wprep_kernel<<<385, 128>>>(W1r0, W1r1, W2r0, W2r1, Wm1, b2r0, b2r1, gb + OFF_BF);

    // --- conv1: merged gather + single dual-GEMM launch ---
    gather2_kernel<<<gat_grid, 256>>>(xA, xB, 0, 0, row0, csr0, row1, csr1,
                                      sOut0, sIn0, OFF_AGGB,
                                      sOut1, sIn1, OFF_AGGA);
    mma_gemm_dual<<<dim3(gemm_grid, 2), 256, SMEM_BYTES>>>(
        aggB, aggA, w1r0h, w1r0l, w1r1h, w1r1l, b1r0, b1r1,
        gb + OFF_HB, gb + OFF_HA, M);

    // --- conv2: merged gather ---
    gather2_kernel<<<gat_grid, 256>>>(nullptr, nullptr, OFF_HA, OFF_HB,
                                      row0, csr0, row1, csr1,
                                      sOut0, sIn0, OFF_AGGB,
                                      sOut1, sIn1, OFF_AGGA);

    // --- fused conv2+MLP GEMM + BN stats epilogue ---
    mma_gemm_fused<<<gemm_grid, 256, SMEM_BYTES>>>(
        aggA, aggB, wfah, wfal, wfbh, wfbl, gb + OFF_BF, gb + OFF_T,
        gb + OFF_STATS, M);

    // --- head (BN finalize inline) ---
    final_kernel<<<(M + 7) / 8, 256>>>(Wm2, gamma, beta, out, M);
}